// round 9
// baseline (speedup 1.0000x reference)
#include <cuda_runtime.h>
#include <cuda_fp16.h>
#include <cstdint>
#include <math.h>

// Problem constants
#define BB 2
#define TT 2048
#define CC 2048
#define HH 16
#define DD 128
#define MM (BB*TT)          // 4096
#define N_QKV (3*CC)        // 6144

// Scratch (static device globals; no runtime allocation allowed)
__device__ float g_invfreq[DD/2];

// fp16 operands
__device__ __half g_xh[(size_t)MM * CC];
__device__ __half g_xl[(size_t)MM * CC];
__device__ __half g_yh[(size_t)MM * CC];
__device__ __half g_yl[(size_t)MM * CC];
__device__ __half g_wqt_h[(size_t)N_QKV * CC];   // w_qkv^T [N,K] hi only
__device__ __half g_wot_h[(size_t)CC * CC];      // w_out^T hi only
__device__ __half g_qh[(size_t)MM * CC];         // Q hi only, [B,H,T,D]
__device__ __half g_kh[(size_t)MM * CC];
__device__ __half g_kl[(size_t)MM * CC];
__device__ __half g_vh[(size_t)MM * CC];
__device__ __half g_vl[(size_t)MM * CC];

// ===========================================================================
__device__ __forceinline__ uint32_t smem_u32(const void* p) {
    uint32_t a;
    asm("{ .reg .u64 t; cvta.to.shared.u64 t, %1; cvt.u32.u64 %0, t; }"
        : "=r"(a) : "l"(p));
    return a;
}
#define CP_ASYNC16(dst, src) \
    asm volatile("cp.async.cg.shared.global [%0], [%1], 16;" :: "r"(dst), "l"(src))
#define CP_COMMIT() asm volatile("cp.async.commit_group;" ::: "memory")
#define CP_WAIT(n)  asm volatile("cp.async.wait_group %0;" :: "n"(n) : "memory")

__device__ __forceinline__ void ldsm4(uint32_t* r, uint32_t addr) {
    asm volatile("ldmatrix.sync.aligned.m8n8.x4.shared.b16 {%0,%1,%2,%3}, [%4];"
        : "=r"(r[0]), "=r"(r[1]), "=r"(r[2]), "=r"(r[3]) : "r"(addr));
}
__device__ __forceinline__ void ldsm4t(uint32_t* r, uint32_t addr) {
    asm volatile("ldmatrix.sync.aligned.m8n8.x4.trans.shared.b16 {%0,%1,%2,%3}, [%4];"
        : "=r"(r[0]), "=r"(r[1]), "=r"(r[2]), "=r"(r[3]) : "r"(addr));
}
__device__ __forceinline__ void mma_f16(float* d, const uint32_t* a, const uint32_t* b) {
    asm volatile("mma.sync.aligned.m16n8k16.row.col.f32.f16.f16.f32 "
        "{%0,%1,%2,%3}, {%4,%5,%6,%7}, {%8,%9}, {%0,%1,%2,%3};"
        : "+f"(d[0]), "+f"(d[1]), "+f"(d[2]), "+f"(d[3])
        : "r"(a[0]), "r"(a[1]), "r"(a[2]), "r"(a[3]), "r"(b[0]), "r"(b[1]));
}

// ===========================================================================
__global__ void init_invfreq_kernel() {
    int i = threadIdx.x;
    if (i < DD/2) {
        double e = (double)(2*i) / (double)DD;
        g_invfreq[i] = (float)(1.0 / pow(10000.0, e));
    }
}

// fp32 -> (fp16 hi, fp16 lo)
__global__ __launch_bounds__(256)
void split_convert_kernel(const float* __restrict__ src,
                          __half* __restrict__ hi,
                          __half* __restrict__ lo, int n)
{
    int i = blockIdx.x * 256 + threadIdx.x;
    if (i < n) {
        float v = src[i];
        __half h = __float2half(v);
        hi[i] = h;
        lo[i] = __float2half(v - __half2float(h));
    }
}

// W[K][N] -> Th[N][K] transposed fp16 hi only
__global__ __launch_bounds__(256)
void transpose_split_kernel(const float* __restrict__ W,
                            __half* __restrict__ Th, int K, int N)
{
    __shared__ float tile[32][33];
    int n0 = blockIdx.x * 32, k0 = blockIdx.y * 32;
    int tx = threadIdx.x & 31, ty = threadIdx.x >> 5;
    #pragma unroll
    for (int r = 0; r < 4; r++)
        tile[ty + r*8][tx] = W[(size_t)(k0 + ty + r*8)*N + n0 + tx];
    __syncthreads();
    #pragma unroll
    for (int r = 0; r < 4; r++) {
        float v = tile[tx][ty + r*8];
        Th[(size_t)(n0 + ty + r*8)*K + k0 + tx] = __float2half(v);
    }
}

// ===========================================================================
// HMMA fp16 2-product GEMM: C = (Ah+Al)[M,K] . Bh[N,K]^T
// CTA tile 128x128, 256 threads (8 warps 2x4), warp tile 64x32, KC=64.
// FUSED=1: epilogue applies RoPE + fp16 split and writes q/k/v directly
//          (each 128-col N tile == one (matrix, head) slab; rotate_half
//           pairs (d, d^64) are intra-tile).
// ===========================================================================
#define KC 64
#define GT_B 16384
#define STAGE_B (3*GT_B)
#define GH_SMEM (2*STAGE_B)   // 98304
#define SOP 132               // fp32 staging row pitch (floats)

template<int FUSED>
__global__ __launch_bounds__(256, 1)
void gemm_hmma_kernel(const __half* __restrict__ Ah,
                      const __half* __restrict__ Al,
                      const __half* __restrict__ Bh,
                      float* __restrict__ C, int M, int N, int K)
{
    extern __shared__ char sm[];
    const uint32_t sbase = smem_u32(sm);

    const int tid  = threadIdx.x;
    const int wid  = tid >> 5;
    const int lane = tid & 31;
    const int wm = wid >> 2;          // 0..1 -> 64 rows
    const int wn = wid & 3;           // 0..3 -> 32 cols
    const int bm = blockIdx.y * 128;
    const int bn = blockIdx.x * 128;

    const __half* srcs[3] = { Ah + (size_t)bm*K, Al + (size_t)bm*K,
                              Bh + (size_t)bn*K };

    const int aRowB = wm*64 + (lane & 7) + ((lane >> 3) & 1)*8;
    const int aCH   = lane >> 4;
    const int bRowB = wn*32 + ((lane >> 4) & 1)*8 + (lane & 7);
    const int bCH   = (lane >> 3) & 1;

    float acc[4][4][4];
    #pragma unroll
    for (int mt = 0; mt < 4; mt++)
        #pragma unroll
        for (int nt = 0; nt < 4; nt++)
            #pragma unroll
            for (int e = 0; e < 4; e++) acc[mt][nt][e] = 0.f;

    auto load_stage = [&](int buf, int kc) {
        uint32_t stg = sbase + buf*STAGE_B;
        #pragma unroll
        for (int t = 0; t < 3; t++) {
            const __half* sp = srcs[t] + kc*KC;
            uint32_t db = stg + t*GT_B;
            #pragma unroll
            for (int e = 0; e < 4; e++) {
                int idx = e*256 + tid;
                int row = idx >> 3, u = idx & 7;
                uint32_t d = db + row*128 + ((u ^ (row & 7))*16);
                CP_ASYNC16(d, sp + (size_t)row*K + u*8);
            }
        }
    };

    const int nch = K / KC;
    load_stage(0, 0);
    CP_COMMIT();

    for (int c = 0; c < nch; c++) {
        if (c + 1 < nch) {
            load_stage((c+1) & 1, c+1);
            CP_COMMIT();
            CP_WAIT(1);
        } else {
            CP_WAIT(0);
        }
        __syncthreads();

        const uint32_t stg = sbase + (c & 1)*STAGE_B;

        #pragma unroll
        for (int ks = 0; ks < 4; ks++) {
            uint32_t ah[4][4], al[4][4], bh[2][4];
            #pragma unroll
            for (int mt = 0; mt < 4; mt++) {
                int r = aRowB + mt*16;
                uint32_t off = r*128 + (((ks*2 + aCH) ^ (r & 7))*16);
                ldsm4(ah[mt], stg + off);
                ldsm4(al[mt], stg + GT_B + off);
            }
            #pragma unroll
            for (int nt2 = 0; nt2 < 2; nt2++) {
                int r = bRowB + nt2*16;
                uint32_t off = r*128 + (((ks*2 + bCH) ^ (r & 7))*16);
                ldsm4(bh[nt2], stg + 2*GT_B + off);
            }
            #pragma unroll
            for (int mt = 0; mt < 4; mt++) {
                #pragma unroll
                for (int nt = 0; nt < 4; nt++) {
                    const uint32_t* bhp = &bh[nt >> 1][(nt & 1)*2];
                    mma_f16(acc[mt][nt], ah[mt], bhp);
                    mma_f16(acc[mt][nt], al[mt], bhp);
                }
            }
        }
        __syncthreads();
    }

    if (!FUSED) {
        #pragma unroll
        for (int mt = 0; mt < 4; mt++) {
            #pragma unroll
            for (int nt = 0; nt < 4; nt++) {
                int r0 = bm + wm*64 + mt*16 + (lane >> 2);
                int c0 = bn + wn*32 + nt*8 + (lane & 3)*2;
                *(float2*)(C + (size_t)r0*N + c0) =
                    make_float2(acc[mt][nt][0], acc[mt][nt][1]);
                *(float2*)(C + (size_t)(r0+8)*N + c0) =
                    make_float2(acc[mt][nt][2], acc[mt][nt][3]);
            }
        }
        return;
    }

    // ---- FUSED epilogue: stage fp32 tile, apply RoPE+split, write q/k/v ----
    float* so = (float*)sm;           // stage buffers are dead now
    #pragma unroll
    for (int mt = 0; mt < 4; mt++) {
        #pragma unroll
        for (int nt = 0; nt < 4; nt++) {
            int r0 = wm*64 + mt*16 + (lane >> 2);
            int c0 = wn*32 + nt*8 + (lane & 3)*2;
            *(float2*)&so[r0*SOP + c0] =
                make_float2(acc[mt][nt][0], acc[mt][nt][1]);
            *(float2*)&so[(r0+8)*SOP + c0] =
                make_float2(acc[mt][nt][2], acc[mt][nt][3]);
        }
    }
    __syncthreads();

    const int mat = bn >> 11;             // 0=q, 1=k, 2=v
    const int h   = (bn & 2047) >> 7;     // head
    const int cl  = tid & 127;            // local col = d
    const int rg  = tid >> 7;             // 0/1

    const float invf = g_invfreq[cl & 63];
    const float sgn  = (cl < 64) ? -1.f : 1.f;
    const int   cp   = cl ^ 64;

    #pragma unroll 4
    for (int e = 0; e < 64; e++) {
        int r = rg + e*2;
        int m = bm + r;
        int b = m >> 11, t = m & (TT-1);
        size_t o = (((size_t)(b*HH + h))*TT + t)*DD + cl;
        float v0 = so[r*SOP + cl];

        if (mat == 2) {                   // v: plain split
            __half hv = __float2half(v0);
            g_vh[o] = hv;
            g_vl[o] = __float2half(v0 - __half2float(hv));
        } else {                          // q/k: rope
            float vp = so[r*SOP + cp];
            float sn_, cs_;
            sincosf((float)t * invf, &sn_, &cs_);
            float res = v0*cs_ + sgn*vp*sn_;
            if (mat == 0) {
                g_qh[o] = __float2half(res);
            } else {
                __half hk = __float2half(res);
                g_kh[o] = hk;
                g_kl[o] = __float2half(res - __half2float(hk));
            }
        }
    }
}

// ===========================================================================
// HMMA fp16 flash attention (unchanged from R7/R8 winner)
// ===========================================================================
#define AQ 128
#define AK 64
#define SM_Q 32768
#define STG_SZ 65536
#define ATT_SMEM (SM_Q + 2*STG_SZ)   // 163840

__global__ __launch_bounds__(256, 1)
void attn_hmma_kernel()
{
    extern __shared__ char sm[];
    const uint32_t sb = smem_u32(sm);
    const int tid = threadIdx.x, wid = tid >> 5, lane = tid & 31;

    const int qt  = (TT/AQ - 1) - blockIdx.x;
    const int bh  = blockIdx.y;
    const int qt0 = qt * AQ;
    const size_t base = (size_t)bh * TT * DD;
    const __half *qhp = g_qh + base;
    const __half *khp = g_kh + base, *klp = g_kl + base;
    const __half *vhp = g_vh + base, *vlp = g_vl + base;

    #pragma unroll
    for (int e = 0; e < 8; e++) {
        int idx = e*256 + tid;
        int r   = (idx >> 4) & 127;
        int ug  = idx & 15;
        int h2 = ug >> 3, u = ug & 7;
        uint32_t dst = sb + h2*16384 + r*128 + ((u ^ (r & 7))*16);
        CP_ASYNC16(dst, qhp + (size_t)(qt0 + r)*DD + ug*8);
    }

    const int nch = 2*qt + 2;

    auto load_stage = [&](int buf, int j0) {
        uint32_t stg = sb + SM_Q + buf*STG_SZ;
        #pragma unroll
        for (int e = 0; e < 8; e++) {
            int idx = e*256 + tid;
            int arr = idx >> 10;
            int r   = (idx >> 4) & 63;
            int ug  = idx & 15;
            int h2 = ug >> 3, u = ug & 7;
            uint32_t dst = stg + arr*16384 + h2*8192 + r*128 + ((u ^ (r & 7))*16);
            const __half* s = (arr ? klp : khp) + (size_t)(j0 + r)*DD + ug*8;
            CP_ASYNC16(dst, s);
        }
        #pragma unroll
        for (int e = 0; e < 8; e++) {
            int idx = e*256 + tid;
            int arr = idx >> 10;
            int r   = (idx >> 4) & 63;
            int ug  = idx & 15;
            int h2 = ug >> 3, u = ug & 7;
            uint32_t dst = stg + 32768 + arr*16384 + h2*8192 + r*128 + ((u ^ (r & 7))*16);
            const __half* s = (arr ? vlp : vhp) + (size_t)(j0 + r)*DD + ug*8;
            CP_ASYNC16(dst, s);
        }
    };

    load_stage(0, 0);
    CP_COMMIT();
    if (nch > 1) { load_stage(1, AK); CP_COMMIT(); }

    const int rowblk = (wid < 4) ? wid : (11 - wid);
    const int wrow0 = rowblk * 16;
    const int gq0 = qt0 + wrow0;

    float yac[16][4];
    #pragma unroll
    for (int nf = 0; nf < 16; nf++)
        #pragma unroll
        for (int e = 0; e < 4; e++) yac[nf][e] = 0.f;
    float mi[2] = {-1e30f, -1e30f}, li[2] = {0.f, 0.f};

    const float scale = 0.08838834764831845f;

    for (int c = 0; c < nch; c++) {
        const int j0 = c * AK;
        if (c + 1 < nch) { CP_WAIT(1); } else { CP_WAIT(0); }
        __syncthreads();

        const uint32_t stg = sb + SM_Q + (c & 1)*STG_SZ;

        if (j0 < gq0 + 16) {
            float sa[8][4];
            #pragma unroll
            for (int nf = 0; nf < 8; nf++)
                #pragma unroll
                for (int e = 0; e < 4; e++) sa[nf][e] = 0.f;

            #pragma unroll
            for (int kh2 = 0; kh2 < 2; kh2++) {
                uint32_t qb  = sb + kh2*16384;
                uint32_t kb  = stg + kh2*8192;
                uint32_t kbl = stg + 16384 + kh2*8192;
                #pragma unroll
                for (int ks = 0; ks < 4; ks++) {
                    int ar = wrow0 + (lane & 7) + ((lane >> 3) & 1)*8;
                    int au = ks*2 + (lane >> 4);
                    uint32_t aoff = ar*128 + ((au ^ (ar & 7))*16);
                    uint32_t Qh4[4];
                    ldsm4(Qh4, qb + aoff);
                    int br_ = ((lane >> 4) & 1)*8 + (lane & 7);
                    int bu  = ks*2 + ((lane >> 3) & 1);
                    #pragma unroll
                    for (int nb = 0; nb < 4; nb++) {
                        int r = br_ + nb*16;
                        uint32_t boff = r*128 + ((bu ^ (r & 7))*16);
                        uint32_t Kh4[4], Kl4[4];
                        ldsm4(Kh4, kb + boff);
                        ldsm4(Kl4, kbl + boff);
                        mma_f16(sa[2*nb],   Qh4, Kh4);
                        mma_f16(sa[2*nb],   Qh4, Kl4);
                        mma_f16(sa[2*nb+1], Qh4, Kh4+2);
                        mma_f16(sa[2*nb+1], Qh4, Kl4+2);
                    }
                }
            }

            #pragma unroll
            for (int nf = 0; nf < 8; nf++)
                #pragma unroll
                for (int e = 0; e < 4; e++) sa[nf][e] *= scale;
            if (j0 + 63 > gq0) {
                #pragma unroll
                for (int nf = 0; nf < 8; nf++)
                    #pragma unroll
                    for (int e = 0; e < 4; e++) {
                        int row = gq0 + (lane >> 2) + (e >> 1)*8;
                        int col = j0 + nf*8 + 2*(lane & 3) + (e & 1);
                        if (col > row) sa[nf][e] = -1e30f;
                    }
            }

            #pragma unroll
            for (int rh = 0; rh < 2; rh++) {
                float m = -1e30f;
                #pragma unroll
                for (int nf = 0; nf < 8; nf++)
                    m = fmaxf(m, fmaxf(sa[nf][rh*2], sa[nf][rh*2+1]));
                m = fmaxf(m, __shfl_xor_sync(0xffffffffu, m, 1));
                m = fmaxf(m, __shfl_xor_sync(0xffffffffu, m, 2));
                float mnew = fmaxf(mi[rh], m);
                float corr = __expf(mi[rh] - mnew);
                float rs = 0.f;
                #pragma unroll
                for (int nf = 0; nf < 8; nf++) {
                    float p0 = __expf(sa[nf][rh*2]   - mnew);
                    float p1 = __expf(sa[nf][rh*2+1] - mnew);
                    sa[nf][rh*2] = p0; sa[nf][rh*2+1] = p1;
                    rs += p0 + p1;
                }
                rs += __shfl_xor_sync(0xffffffffu, rs, 1);
                rs += __shfl_xor_sync(0xffffffffu, rs, 2);
                li[rh] = li[rh]*corr + rs;
                mi[rh] = mnew;
                #pragma unroll
                for (int nf = 0; nf < 16; nf++) {
                    yac[nf][rh*2]   *= corr;
                    yac[nf][rh*2+1] *= corr;
                }
            }

            uint32_t pH[4][4];
            #pragma unroll
            for (int j = 0; j < 4; j++) {
                #pragma unroll
                for (int q = 0; q < 4; q++) {
                    int f = 2*j + (q >> 1);
                    int o = (q & 1)*2;
                    __half2 hp;
                    hp.x = __float2half(sa[f][o]);
                    hp.y = __float2half(sa[f][o+1]);
                    pH[j][q] = *(uint32_t*)&hp;
                }
            }

            const uint32_t vb  = stg + 32768;
            const uint32_t vbl = stg + 49152;
            #pragma unroll
            for (int ks = 0; ks < 4; ks++) {
                #pragma unroll
                for (int db = 0; db < 8; db++) {
                    int m4 = lane >> 3;
                    int j = ks*16 + (m4 & 1)*8 + (lane & 7);
                    int un = (db & 3)*2 + (m4 >> 1);
                    uint32_t off = (db >> 2)*8192 + j*128 + ((un ^ (j & 7))*16);
                    uint32_t Vh4[4], Vl4[4];
                    ldsm4t(Vh4, vb + off);
                    ldsm4t(Vl4, vbl + off);
                    mma_f16(yac[db*2],   pH[ks], Vh4);
                    mma_f16(yac[db*2],   pH[ks], Vl4);
                    mma_f16(yac[db*2+1], pH[ks], Vh4+2);
                    mma_f16(yac[db*2+1], pH[ks], Vl4+2);
                }
            }
        }

        __syncthreads();
        if (c + 2 < nch) { load_stage(c & 1, (c+2)*AK); CP_COMMIT(); }
    }

    const int b = bh >> 4, h = bh & 15;
    #pragma unroll
    for (int rh = 0; rh < 2; rh++) {
        float inv = 1.f / li[rh];
        int t = gq0 + (lane >> 2) + rh*8;
        size_t rowo = ((size_t)(b*TT + t))*CC + h*DD;
        #pragma unroll
        for (int nf = 0; nf < 16; nf++) {
            int col = nf*8 + 2*(lane & 3);
            float y0 = yac[nf][rh*2]*inv, y1 = yac[nf][rh*2+1]*inv;
            __half2 hp, lp;
            hp.x = __float2half(y0);
            hp.y = __float2half(y1);
            lp.x = __float2half(y0 - __half2float(hp.x));
            lp.y = __float2half(y1 - __half2float(hp.y));
            *(__half2*)(g_yh + rowo + col) = hp;
            *(__half2*)(g_yl + rowo + col) = lp;
        }
    }
}

// ===========================================================================
extern "C" void kernel_launch(void* const* d_in, const int* in_sizes, int n_in,
                              void* d_out, int out_size)
{
    const float* x     = (const float*)d_in[0];
    const float* w_qkv = (const float*)d_in[1];
    const float* w_out = (const float*)d_in[2];
    float* out = (float*)d_out;

    __half *xh, *xl, *yh, *yl, *wqh, *woh;
    cudaGetSymbolAddress((void**)&xh, g_xh);
    cudaGetSymbolAddress((void**)&xl, g_xl);
    cudaGetSymbolAddress((void**)&yh, g_yh);
    cudaGetSymbolAddress((void**)&yl, g_yl);
    cudaGetSymbolAddress((void**)&wqh, g_wqt_h);
    cudaGetSymbolAddress((void**)&woh, g_wot_h);

    static int attr_set = 0;
    if (!attr_set) {
        cudaFuncSetAttribute(gemm_hmma_kernel<0>,
                             cudaFuncAttributeMaxDynamicSharedMemorySize, GH_SMEM);
        cudaFuncSetAttribute(gemm_hmma_kernel<1>,
                             cudaFuncAttributeMaxDynamicSharedMemorySize, GH_SMEM);
        cudaFuncSetAttribute(attn_hmma_kernel,
                             cudaFuncAttributeMaxDynamicSharedMemorySize, ATT_SMEM);
        attr_set = 1;
    }

    init_invfreq_kernel<<<1, 64>>>();

    split_convert_kernel<<<(MM*CC + 255)/256, 256>>>(x, xh, xl, MM*CC);
    transpose_split_kernel<<<dim3(N_QKV/32, CC/32), 256>>>(w_qkv, wqh, CC, N_QKV);
    transpose_split_kernel<<<dim3(CC/32, CC/32), 256>>>(w_out, woh, CC, CC);

    // qkv = x @ w_qkv, fused RoPE + split epilogue -> g_qh/kh/kl/vh/vl
    gemm_hmma_kernel<1><<<dim3(N_QKV/128, MM/128), 256, GH_SMEM>>>(
        xh, xl, wqh, nullptr, MM, N_QKV, CC);

    // HMMA flash attention -> yh/yl [B,T,C]
    attn_hmma_kernel<<<dim3(TT/AQ, BB*HH), 256, ATT_SMEM>>>();

    // out = y @ w_out
    gemm_hmma_kernel<0><<<dim3(CC/128, MM/128), 256, GH_SMEM>>>(
        yh, yl, woh, out, MM, CC, CC);
}

// round 10
// speedup vs baseline: 1.1037x; 1.1037x over previous
#include <cuda_runtime.h>
#include <cuda_fp16.h>
#include <cstdint>
#include <math.h>

// Problem constants
#define BB 2
#define TT 2048
#define CC 2048
#define HH 16
#define DD 128
#define MM (BB*TT)          // 4096
#define N_QKV (3*CC)        // 6144

// Scratch (static device globals; no runtime allocation allowed)
__device__ float g_qkv[(size_t)MM * N_QKV];
__device__ float g_invfreq[DD/2];

// fp16 operands
__device__ __half g_xh[(size_t)MM * CC];
__device__ __half g_xl[(size_t)MM * CC];
__device__ __half g_yh[(size_t)MM * CC];
__device__ __half g_yl[(size_t)MM * CC];
__device__ __half g_wqt_h[(size_t)N_QKV * CC];   // w_qkv^T [N,K] hi only
__device__ __half g_wot_h[(size_t)CC * CC];      // w_out^T hi only
__device__ __half g_qh[(size_t)MM * CC];         // [B,H,T,D] fp16
__device__ __half g_kh[(size_t)MM * CC];
__device__ __half g_vh[(size_t)MM * CC];

// ===========================================================================
__device__ __forceinline__ uint32_t smem_u32(const void* p) {
    uint32_t a;
    asm("{ .reg .u64 t; cvta.to.shared.u64 t, %1; cvt.u32.u64 %0, t; }"
        : "=r"(a) : "l"(p));
    return a;
}
#define CP_ASYNC16(dst, src) \
    asm volatile("cp.async.cg.shared.global [%0], [%1], 16;" :: "r"(dst), "l"(src))
#define CP_COMMIT() asm volatile("cp.async.commit_group;" ::: "memory")
#define CP_WAIT(n)  asm volatile("cp.async.wait_group %0;" :: "n"(n) : "memory")

__device__ __forceinline__ void ldsm4(uint32_t* r, uint32_t addr) {
    asm volatile("ldmatrix.sync.aligned.m8n8.x4.shared.b16 {%0,%1,%2,%3}, [%4];"
        : "=r"(r[0]), "=r"(r[1]), "=r"(r[2]), "=r"(r[3]) : "r"(addr));
}
__device__ __forceinline__ void ldsm4t(uint32_t* r, uint32_t addr) {
    asm volatile("ldmatrix.sync.aligned.m8n8.x4.trans.shared.b16 {%0,%1,%2,%3}, [%4];"
        : "=r"(r[0]), "=r"(r[1]), "=r"(r[2]), "=r"(r[3]) : "r"(addr));
}
__device__ __forceinline__ void mma_f16(float* d, const uint32_t* a, const uint32_t* b) {
    asm volatile("mma.sync.aligned.m16n8k16.row.col.f32.f16.f16.f32 "
        "{%0,%1,%2,%3}, {%4,%5,%6,%7}, {%8,%9}, {%0,%1,%2,%3};"
        : "+f"(d[0]), "+f"(d[1]), "+f"(d[2]), "+f"(d[3])
        : "r"(a[0]), "r"(a[1]), "r"(a[2]), "r"(a[3]), "r"(b[0]), "r"(b[1]));
}

// ===========================================================================
__global__ void init_invfreq_kernel() {
    int i = threadIdx.x;
    if (i < DD/2) {
        double e = (double)(2*i) / (double)DD;
        g_invfreq[i] = (float)(1.0 / pow(10000.0, e));
    }
}

// fp32 -> (fp16 hi, fp16 lo)
__global__ __launch_bounds__(256)
void split_convert_kernel(const float* __restrict__ src,
                          __half* __restrict__ hi,
                          __half* __restrict__ lo, int n)
{
    int i = blockIdx.x * 256 + threadIdx.x;
    if (i < n) {
        float v = src[i];
        __half h = __float2half(v);
        hi[i] = h;
        lo[i] = __float2half(v - __half2float(h));
    }
}

// W[K][N] -> Th[N][K] transposed fp16 hi only
__global__ __launch_bounds__(256)
void transpose_split_kernel(const float* __restrict__ W,
                            __half* __restrict__ Th, int K, int N)
{
    __shared__ float tile[32][33];
    int n0 = blockIdx.x * 32, k0 = blockIdx.y * 32;
    int tx = threadIdx.x & 31, ty = threadIdx.x >> 5;
    #pragma unroll
    for (int r = 0; r < 4; r++)
        tile[ty + r*8][tx] = W[(size_t)(k0 + ty + r*8)*N + n0 + tx];
    __syncthreads();
    #pragma unroll
    for (int r = 0; r < 4; r++) {
        float v = tile[tx][ty + r*8];
        Th[(size_t)(n0 + ty + r*8)*K + k0 + tx] = __float2half(v);
    }
}

// ===========================================================================
// HMMA fp16 2-product GEMM: C = (Ah+Al)[M,K] . Bh[N,K]^T
// CTA tile 128x128, 256 threads (8 warps 2x4), warp tile 64x32, KC=64.
// ===========================================================================
#define KC 64
#define GT_B 16384
#define STAGE_B (3*GT_B)
#define GH_SMEM (2*STAGE_B)   // 98304

__global__ __launch_bounds__(256, 1)
void gemm_hmma_kernel(const __half* __restrict__ Ah,
                      const __half* __restrict__ Al,
                      const __half* __restrict__ Bh,
                      float* __restrict__ C, int M, int N, int K)
{
    extern __shared__ char sm[];
    const uint32_t sbase = smem_u32(sm);

    const int tid  = threadIdx.x;
    const int wid  = tid >> 5;
    const int lane = tid & 31;
    const int wm = wid >> 2;
    const int wn = wid & 3;
    const int bm = blockIdx.y * 128;
    const int bn = blockIdx.x * 128;

    const __half* srcs[3] = { Ah + (size_t)bm*K, Al + (size_t)bm*K,
                              Bh + (size_t)bn*K };

    const int aRowB = wm*64 + (lane & 7) + ((lane >> 3) & 1)*8;
    const int aCH   = lane >> 4;
    const int bRowB = wn*32 + ((lane >> 4) & 1)*8 + (lane & 7);
    const int bCH   = (lane >> 3) & 1;

    float acc[4][4][4];
    #pragma unroll
    for (int mt = 0; mt < 4; mt++)
        #pragma unroll
        for (int nt = 0; nt < 4; nt++)
            #pragma unroll
            for (int e = 0; e < 4; e++) acc[mt][nt][e] = 0.f;

    auto load_stage = [&](int buf, int kc) {
        uint32_t stg = sbase + buf*STAGE_B;
        #pragma unroll
        for (int t = 0; t < 3; t++) {
            const __half* sp = srcs[t] + kc*KC;
            uint32_t db = stg + t*GT_B;
            #pragma unroll
            for (int e = 0; e < 4; e++) {
                int idx = e*256 + tid;
                int row = idx >> 3, u = idx & 7;
                uint32_t d = db + row*128 + ((u ^ (row & 7))*16);
                CP_ASYNC16(d, sp + (size_t)row*K + u*8);
            }
        }
    };

    const int nch = K / KC;
    load_stage(0, 0);
    CP_COMMIT();

    for (int c = 0; c < nch; c++) {
        if (c + 1 < nch) {
            load_stage((c+1) & 1, c+1);
            CP_COMMIT();
            CP_WAIT(1);
        } else {
            CP_WAIT(0);
        }
        __syncthreads();

        const uint32_t stg = sbase + (c & 1)*STAGE_B;

        #pragma unroll
        for (int ks = 0; ks < 4; ks++) {
            uint32_t ah[4][4], al[4][4], bh[2][4];
            #pragma unroll
            for (int mt = 0; mt < 4; mt++) {
                int r = aRowB + mt*16;
                uint32_t off = r*128 + (((ks*2 + aCH) ^ (r & 7))*16);
                ldsm4(ah[mt], stg + off);
                ldsm4(al[mt], stg + GT_B + off);
            }
            #pragma unroll
            for (int nt2 = 0; nt2 < 2; nt2++) {
                int r = bRowB + nt2*16;
                uint32_t off = r*128 + (((ks*2 + bCH) ^ (r & 7))*16);
                ldsm4(bh[nt2], stg + 2*GT_B + off);
            }
            #pragma unroll
            for (int mt = 0; mt < 4; mt++) {
                #pragma unroll
                for (int nt = 0; nt < 4; nt++) {
                    const uint32_t* bhp = &bh[nt >> 1][(nt & 1)*2];
                    mma_f16(acc[mt][nt], ah[mt], bhp);
                    mma_f16(acc[mt][nt], al[mt], bhp);
                }
            }
        }
        __syncthreads();
    }

    #pragma unroll
    for (int mt = 0; mt < 4; mt++) {
        #pragma unroll
        for (int nt = 0; nt < 4; nt++) {
            int r0 = bm + wm*64 + mt*16 + (lane >> 2);
            int c0 = bn + wn*32 + nt*8 + (lane & 3)*2;
            *(float2*)(C + (size_t)r0*N + c0) =
                make_float2(acc[mt][nt][0], acc[mt][nt][1]);
            *(float2*)(C + (size_t)(r0+8)*N + c0) =
                make_float2(acc[mt][nt][2], acc[mt][nt][3]);
        }
    }
}

// ===========================================================================
// RoPE + split: q/k/v single fp16, [B,H,T,D]
// ===========================================================================
__global__ __launch_bounds__(256)
void rope_split_kernel()
{
    int idx = blockIdx.x * blockDim.x + threadIdx.x;
    int m = idx >> 11;
    int c = idx & 2047;
    int t = m & (TT-1);
    int d = c & (DD-1);
    int dm = d & 63;

    float ang = (float)t * g_invfreq[dm];
    float sn, cs;
    sincosf(ang, &sn, &cs);

    size_t base = (size_t)m * N_QKV;
    float qv = g_qkv[base + c];
    float kv = g_qkv[base + CC + c];
    float vv = g_qkv[base + 2*CC + c];

    int c2 = (d < 64) ? (c + 64) : (c - 64);
    float sgn = (d < 64) ? -1.f : 1.f;
    float qr = g_qkv[base + c2];
    float kr = g_qkv[base + CC + c2];

    float qo = qv*cs + sgn*qr*sn;
    float ko = kv*cs + sgn*kr*sn;

    int b = m >> 11;
    int h = c >> 7;
    size_t o = (((size_t)(b*HH + h))*TT + t)*DD + d;

    g_qh[o] = __float2half(qo);
    g_kh[o] = __float2half(ko);
    g_vh[o] = __float2half(vv);
}

// ===========================================================================
// HMMA fp16 flash attention, single-precision K/V (1 product per phase).
// BQ=128, BK=64, 8 warps x 16 q-rows, SMSP-balancing warp permutation.
// Smem: Q 32KB + 2 stages x (K 16KB + V 16KB) = 96KB.
// ===========================================================================
#define AQ 128
#define AK 64
#define SM_Q 32768
#define STG_SZ 32768
#define ATT_SMEM (SM_Q + 2*STG_SZ)   // 98304

__global__ __launch_bounds__(256, 1)
void attn_hmma_kernel()
{
    extern __shared__ char sm[];
    const uint32_t sb = smem_u32(sm);
    const int tid = threadIdx.x, wid = tid >> 5, lane = tid & 31;

    const int qt  = (TT/AQ - 1) - blockIdx.x;
    const int bh  = blockIdx.y;
    const int qt0 = qt * AQ;
    const size_t base = (size_t)bh * TT * DD;
    const __half *qhp = g_qh + base;
    const __half *khp = g_kh + base;
    const __half *vhp = g_vh + base;

    // Q tile: 128 rows x 16 units (two 64-col halves of 16KB)
    #pragma unroll
    for (int e = 0; e < 8; e++) {
        int idx = e*256 + tid;              // 0..2047
        int r   = (idx >> 4) & 127;
        int ug  = idx & 15;
        int h2 = ug >> 3, u = ug & 7;
        uint32_t dst = sb + h2*16384 + r*128 + ((u ^ (r & 7))*16);
        CP_ASYNC16(dst, qhp + (size_t)(qt0 + r)*DD + ug*8);
    }

    const int nch = 2*qt + 2;

    auto load_stage = [&](int buf, int j0) {
        uint32_t stg = sb + SM_Q + buf*STG_SZ;
        #pragma unroll
        for (int e = 0; e < 4; e++) {       // K: 64 rows x 16 units
            int idx = e*256 + tid;          // 0..1023
            int r   = (idx >> 4) & 63;
            int ug  = idx & 15;
            int h2 = ug >> 3, u = ug & 7;
            uint32_t dst = stg + h2*8192 + r*128 + ((u ^ (r & 7))*16);
            CP_ASYNC16(dst, khp + (size_t)(j0 + r)*DD + ug*8);
        }
        #pragma unroll
        for (int e = 0; e < 4; e++) {       // V
            int idx = e*256 + tid;
            int r   = (idx >> 4) & 63;
            int ug  = idx & 15;
            int h2 = ug >> 3, u = ug & 7;
            uint32_t dst = stg + 16384 + h2*8192 + r*128 + ((u ^ (r & 7))*16);
            CP_ASYNC16(dst, vhp + (size_t)(j0 + r)*DD + ug*8);
        }
    };

    load_stage(0, 0);
    CP_COMMIT();
    if (nch > 1) { load_stage(1, AK); CP_COMMIT(); }

    // SMSP-balancing permutation: warps (s, s+4) row-blocks sum to 7
    const int rowblk = (wid < 4) ? wid : (11 - wid);
    const int wrow0 = rowblk * 16;
    const int gq0 = qt0 + wrow0;

    float yac[16][4];
    #pragma unroll
    for (int nf = 0; nf < 16; nf++)
        #pragma unroll
        for (int e = 0; e < 4; e++) yac[nf][e] = 0.f;
    float mi[2] = {-1e30f, -1e30f}, li[2] = {0.f, 0.f};

    const float scale = 0.08838834764831845f;

    for (int c = 0; c < nch; c++) {
        const int j0 = c * AK;
        if (c + 1 < nch) { CP_WAIT(1); } else { CP_WAIT(0); }
        __syncthreads();

        const uint32_t stg = sb + SM_Q + (c & 1)*STG_SZ;

        if (j0 < gq0 + 16) {
            float sa[8][4];
            #pragma unroll
            for (int nf = 0; nf < 8; nf++)
                #pragma unroll
                for (int e = 0; e < 4; e++) sa[nf][e] = 0.f;

            #pragma unroll
            for (int kh2 = 0; kh2 < 2; kh2++) {
                uint32_t qb = sb + kh2*16384;
                uint32_t kb = stg + kh2*8192;
                #pragma unroll
                for (int ks = 0; ks < 4; ks++) {
                    int ar = wrow0 + (lane & 7) + ((lane >> 3) & 1)*8;
                    int au = ks*2 + (lane >> 4);
                    uint32_t aoff = ar*128 + ((au ^ (ar & 7))*16);
                    uint32_t Qh4[4];
                    ldsm4(Qh4, qb + aoff);
                    int br_ = ((lane >> 4) & 1)*8 + (lane & 7);
                    int bu  = ks*2 + ((lane >> 3) & 1);
                    #pragma unroll
                    for (int nb = 0; nb < 4; nb++) {
                        int r = br_ + nb*16;
                        uint32_t boff = r*128 + ((bu ^ (r & 7))*16);
                        uint32_t Kh4[4];
                        ldsm4(Kh4, kb + boff);
                        mma_f16(sa[2*nb],   Qh4, Kh4);
                        mma_f16(sa[2*nb+1], Qh4, Kh4+2);
                    }
                }
            }

            #pragma unroll
            for (int nf = 0; nf < 8; nf++)
                #pragma unroll
                for (int e = 0; e < 4; e++) sa[nf][e] *= scale;
            if (j0 + 63 > gq0) {
                #pragma unroll
                for (int nf = 0; nf < 8; nf++)
                    #pragma unroll
                    for (int e = 0; e < 4; e++) {
                        int row = gq0 + (lane >> 2) + (e >> 1)*8;
                        int col = j0 + nf*8 + 2*(lane & 3) + (e & 1);
                        if (col > row) sa[nf][e] = -1e30f;
                    }
            }

            #pragma unroll
            for (int rh = 0; rh < 2; rh++) {
                float m = -1e30f;
                #pragma unroll
                for (int nf = 0; nf < 8; nf++)
                    m = fmaxf(m, fmaxf(sa[nf][rh*2], sa[nf][rh*2+1]));
                m = fmaxf(m, __shfl_xor_sync(0xffffffffu, m, 1));
                m = fmaxf(m, __shfl_xor_sync(0xffffffffu, m, 2));
                float mnew = fmaxf(mi[rh], m);
                float corr = __expf(mi[rh] - mnew);
                float rs = 0.f;
                #pragma unroll
                for (int nf = 0; nf < 8; nf++) {
                    float p0 = __expf(sa[nf][rh*2]   - mnew);
                    float p1 = __expf(sa[nf][rh*2+1] - mnew);
                    sa[nf][rh*2] = p0; sa[nf][rh*2+1] = p1;
                    rs += p0 + p1;
                }
                rs += __shfl_xor_sync(0xffffffffu, rs, 1);
                rs += __shfl_xor_sync(0xffffffffu, rs, 2);
                li[rh] = li[rh]*corr + rs;
                mi[rh] = mnew;
                #pragma unroll
                for (int nf = 0; nf < 16; nf++) {
                    yac[nf][rh*2]   *= corr;
                    yac[nf][rh*2+1] *= corr;
                }
            }

            uint32_t pH[4][4];
            #pragma unroll
            for (int j = 0; j < 4; j++) {
                #pragma unroll
                for (int q = 0; q < 4; q++) {
                    int f = 2*j + (q >> 1);
                    int o = (q & 1)*2;
                    __half2 hp;
                    hp.x = __float2half(sa[f][o]);
                    hp.y = __float2half(sa[f][o+1]);
                    pH[j][q] = *(uint32_t*)&hp;
                }
            }

            const uint32_t vb = stg + 16384;
            #pragma unroll
            for (int ks = 0; ks < 4; ks++) {
                #pragma unroll
                for (int db = 0; db < 8; db++) {
                    int m4 = lane >> 3;
                    int j = ks*16 + (m4 & 1)*8 + (lane & 7);
                    int un = (db & 3)*2 + (m4 >> 1);
                    uint32_t off = (db >> 2)*8192 + j*128 + ((un ^ (j & 7))*16);
                    uint32_t Vh4[4];
                    ldsm4t(Vh4, vb + off);
                    mma_f16(yac[db*2],   pH[ks], Vh4);
                    mma_f16(yac[db*2+1], pH[ks], Vh4+2);
                }
            }
        }

        __syncthreads();
        if (c + 2 < nch) { load_stage(c & 1, (c+2)*AK); CP_COMMIT(); }
    }

    // epilogue: normalize, split fp16 hi/lo for GEMM2, write [B,T,C]
    const int b = bh >> 4, h = bh & 15;
    #pragma unroll
    for (int rh = 0; rh < 2; rh++) {
        float inv = 1.f / li[rh];
        int t = gq0 + (lane >> 2) + rh*8;
        size_t rowo = ((size_t)(b*TT + t))*CC + h*DD;
        #pragma unroll
        for (int nf = 0; nf < 16; nf++) {
            int col = nf*8 + 2*(lane & 3);
            float y0 = yac[nf][rh*2]*inv, y1 = yac[nf][rh*2+1]*inv;
            __half2 hp, lp;
            hp.x = __float2half(y0);
            hp.y = __float2half(y1);
            lp.x = __float2half(y0 - __half2float(hp.x));
            lp.y = __float2half(y1 - __half2float(hp.y));
            *(__half2*)(g_yh + rowo + col) = hp;
            *(__half2*)(g_yl + rowo + col) = lp;
        }
    }
}

// ===========================================================================
extern "C" void kernel_launch(void* const* d_in, const int* in_sizes, int n_in,
                              void* d_out, int out_size)
{
    const float* x     = (const float*)d_in[0];
    const float* w_qkv = (const float*)d_in[1];
    const float* w_out = (const float*)d_in[2];
    float* out = (float*)d_out;

    float *qkv_ptr;
    __half *xh, *xl, *yh, *yl, *wqh, *woh;
    cudaGetSymbolAddress((void**)&qkv_ptr, g_qkv);
    cudaGetSymbolAddress((void**)&xh, g_xh);
    cudaGetSymbolAddress((void**)&xl, g_xl);
    cudaGetSymbolAddress((void**)&yh, g_yh);
    cudaGetSymbolAddress((void**)&yl, g_yl);
    cudaGetSymbolAddress((void**)&wqh, g_wqt_h);
    cudaGetSymbolAddress((void**)&woh, g_wot_h);

    static int attr_set = 0;
    if (!attr_set) {
        cudaFuncSetAttribute(gemm_hmma_kernel,
                             cudaFuncAttributeMaxDynamicSharedMemorySize, GH_SMEM);
        cudaFuncSetAttribute(attn_hmma_kernel,
                             cudaFuncAttributeMaxDynamicSharedMemorySize, ATT_SMEM);
        attr_set = 1;
    }

    init_invfreq_kernel<<<1, 64>>>();

    split_convert_kernel<<<(MM*CC + 255)/256, 256>>>(x, xh, xl, MM*CC);
    transpose_split_kernel<<<dim3(N_QKV/32, CC/32), 256>>>(w_qkv, wqh, CC, N_QKV);
    transpose_split_kernel<<<dim3(CC/32, CC/32), 256>>>(w_out, woh, CC, CC);

    // qkv = x @ w_qkv
    gemm_hmma_kernel<<<dim3(N_QKV/128, MM/128), 256, GH_SMEM>>>(
        xh, xl, wqh, qkv_ptr, MM, N_QKV, CC);

    // RoPE + convert to fp16 [B,H,T,D]
    rope_split_kernel<<<(MM*CC)/256, 256>>>();

    // fp16 flash attention -> yh/yl [B,T,C]
    attn_hmma_kernel<<<dim3(TT/AQ, BB*HH), 256, ATT_SMEM>>>();

    // out = y @ w_out
    gemm_hmma_kernel<<<dim3(CC/128, MM/128), 256, GH_SMEM>>>(
        yh, yl, woh, out, MM, CC, CC);
}

// round 11
// speedup vs baseline: 1.7889x; 1.6208x over previous
#include <cuda_runtime.h>
#include <cuda_fp16.h>
#include <cstdint>
#include <math.h>

// Problem constants
#define BB 2
#define TT 2048
#define CC 2048
#define HH 16
#define DD 128
#define MM (BB*TT)          // 4096
#define N_QKV (3*CC)        // 6144

// Scratch (static device globals; no runtime allocation allowed)
__device__ float g_qkv[(size_t)MM * N_QKV];
__device__ float g_invfreq[DD/2];

// fp16 operands (all single precision fp16 now)
__device__ __half g_xh[(size_t)MM * CC];
__device__ __half g_yh[(size_t)MM * CC];         // attention out [B,T,C]
__device__ __half g_wqt_h[(size_t)N_QKV * CC];   // w_qkv^T [N,K]
__device__ __half g_wot_h[(size_t)CC * CC];      // w_out^T
__device__ __half g_qh[(size_t)MM * CC];         // [B,H,T,D]
__device__ __half g_kh[(size_t)MM * CC];
__device__ __half g_vh[(size_t)MM * CC];

// ===========================================================================
__device__ __forceinline__ uint32_t smem_u32(const void* p) {
    uint32_t a;
    asm("{ .reg .u64 t; cvta.to.shared.u64 t, %1; cvt.u32.u64 %0, t; }"
        : "=r"(a) : "l"(p));
    return a;
}
#define CP_ASYNC16(dst, src) \
    asm volatile("cp.async.cg.shared.global [%0], [%1], 16;" :: "r"(dst), "l"(src))
#define CP_COMMIT() asm volatile("cp.async.commit_group;" ::: "memory")
#define CP_WAIT(n)  asm volatile("cp.async.wait_group %0;" :: "n"(n) : "memory")

__device__ __forceinline__ void ldsm4(uint32_t* r, uint32_t addr) {
    asm volatile("ldmatrix.sync.aligned.m8n8.x4.shared.b16 {%0,%1,%2,%3}, [%4];"
        : "=r"(r[0]), "=r"(r[1]), "=r"(r[2]), "=r"(r[3]) : "r"(addr));
}
__device__ __forceinline__ void ldsm4t(uint32_t* r, uint32_t addr) {
    asm volatile("ldmatrix.sync.aligned.m8n8.x4.trans.shared.b16 {%0,%1,%2,%3}, [%4];"
        : "=r"(r[0]), "=r"(r[1]), "=r"(r[2]), "=r"(r[3]) : "r"(addr));
}
__device__ __forceinline__ void mma_f16(float* d, const uint32_t* a, const uint32_t* b) {
    asm volatile("mma.sync.aligned.m16n8k16.row.col.f32.f16.f16.f32 "
        "{%0,%1,%2,%3}, {%4,%5,%6,%7}, {%8,%9}, {%0,%1,%2,%3};"
        : "+f"(d[0]), "+f"(d[1]), "+f"(d[2]), "+f"(d[3])
        : "r"(a[0]), "r"(a[1]), "r"(a[2]), "r"(a[3]), "r"(b[0]), "r"(b[1]));
}

// ===========================================================================
__global__ void init_invfreq_kernel() {
    int i = threadIdx.x;
    if (i < DD/2) {
        double e = (double)(2*i) / (double)DD;
        g_invfreq[i] = (float)(1.0 / pow(10000.0, e));
    }
}

// fp32 -> fp16
__global__ __launch_bounds__(256)
void convert_kernel(const float* __restrict__ src,
                    __half* __restrict__ dst, int n)
{
    int i = blockIdx.x * 256 + threadIdx.x;
    if (i < n) dst[i] = __float2half(src[i]);
}

// W[K][N] -> Th[N][K] transposed fp16
__global__ __launch_bounds__(256)
void transpose_split_kernel(const float* __restrict__ W,
                            __half* __restrict__ Th, int K, int N)
{
    __shared__ float tile[32][33];
    int n0 = blockIdx.x * 32, k0 = blockIdx.y * 32;
    int tx = threadIdx.x & 31, ty = threadIdx.x >> 5;
    #pragma unroll
    for (int r = 0; r < 4; r++)
        tile[ty + r*8][tx] = W[(size_t)(k0 + ty + r*8)*N + n0 + tx];
    __syncthreads();
    #pragma unroll
    for (int r = 0; r < 4; r++) {
        float v = tile[tx][ty + r*8];
        Th[(size_t)(n0 + ty + r*8)*K + k0 + tx] = __float2half(v);
    }
}

// ===========================================================================
// HMMA fp16 GEMM: C = Ah[M,K] . Bh[N,K]^T  (single product)
// CTA tile 128x128, 256 threads (8 warps 2x4), warp tile 64x32, KC=64.
// Stage: A(16K) + B(16K) = 32KB; double-buffered = 64KB. 2 CTAs/SM.
// ===========================================================================
#define KC 64
#define GT_B 16384
#define STAGE_B (2*GT_B)
#define GH_SMEM (2*STAGE_B)   // 65536

__global__ __launch_bounds__(256, 2)
void gemm_hmma_kernel(const __half* __restrict__ Ah,
                      const __half* __restrict__ Bh,
                      float* __restrict__ C, int M, int N, int K)
{
    extern __shared__ char sm[];
    const uint32_t sbase = smem_u32(sm);

    const int tid  = threadIdx.x;
    const int wid  = tid >> 5;
    const int lane = tid & 31;
    const int wm = wid >> 2;
    const int wn = wid & 3;
    const int bm = blockIdx.y * 128;
    const int bn = blockIdx.x * 128;

    const __half* srcs[2] = { Ah + (size_t)bm*K, Bh + (size_t)bn*K };

    const int aRowB = wm*64 + (lane & 7) + ((lane >> 3) & 1)*8;
    const int aCH   = lane >> 4;
    const int bRowB = wn*32 + ((lane >> 4) & 1)*8 + (lane & 7);
    const int bCH   = (lane >> 3) & 1;

    float acc[4][4][4];
    #pragma unroll
    for (int mt = 0; mt < 4; mt++)
        #pragma unroll
        for (int nt = 0; nt < 4; nt++)
            #pragma unroll
            for (int e = 0; e < 4; e++) acc[mt][nt][e] = 0.f;

    auto load_stage = [&](int buf, int kc) {
        uint32_t stg = sbase + buf*STAGE_B;
        #pragma unroll
        for (int t = 0; t < 2; t++) {
            const __half* sp = srcs[t] + kc*KC;
            uint32_t db = stg + t*GT_B;
            #pragma unroll
            for (int e = 0; e < 4; e++) {
                int idx = e*256 + tid;
                int row = idx >> 3, u = idx & 7;
                uint32_t d = db + row*128 + ((u ^ (row & 7))*16);
                CP_ASYNC16(d, sp + (size_t)row*K + u*8);
            }
        }
    };

    const int nch = K / KC;
    load_stage(0, 0);
    CP_COMMIT();

    for (int c = 0; c < nch; c++) {
        if (c + 1 < nch) {
            load_stage((c+1) & 1, c+1);
            CP_COMMIT();
            CP_WAIT(1);
        } else {
            CP_WAIT(0);
        }
        __syncthreads();

        const uint32_t stg = sbase + (c & 1)*STAGE_B;

        #pragma unroll
        for (int ks = 0; ks < 4; ks++) {
            uint32_t ah[4][4], bh[2][4];
            #pragma unroll
            for (int mt = 0; mt < 4; mt++) {
                int r = aRowB + mt*16;
                uint32_t off = r*128 + (((ks*2 + aCH) ^ (r & 7))*16);
                ldsm4(ah[mt], stg + off);
            }
            #pragma unroll
            for (int nt2 = 0; nt2 < 2; nt2++) {
                int r = bRowB + nt2*16;
                uint32_t off = r*128 + (((ks*2 + bCH) ^ (r & 7))*16);
                ldsm4(bh[nt2], stg + GT_B + off);
            }
            #pragma unroll
            for (int mt = 0; mt < 4; mt++) {
                #pragma unroll
                for (int nt = 0; nt < 4; nt++) {
                    const uint32_t* bhp = &bh[nt >> 1][(nt & 1)*2];
                    mma_f16(acc[mt][nt], ah[mt], bhp);
                }
            }
        }
        __syncthreads();
    }

    #pragma unroll
    for (int mt = 0; mt < 4; mt++) {
        #pragma unroll
        for (int nt = 0; nt < 4; nt++) {
            int r0 = bm + wm*64 + mt*16 + (lane >> 2);
            int c0 = bn + wn*32 + nt*8 + (lane & 3)*2;
            *(float2*)(C + (size_t)r0*N + c0) =
                make_float2(acc[mt][nt][0], acc[mt][nt][1]);
            *(float2*)(C + (size_t)(r0+8)*N + c0) =
                make_float2(acc[mt][nt][2], acc[mt][nt][3]);
        }
    }
}

// ===========================================================================
// RoPE + convert: q/k/v single fp16, [B,H,T,D]
// ===========================================================================
__global__ __launch_bounds__(256)
void rope_split_kernel()
{
    int idx = blockIdx.x * blockDim.x + threadIdx.x;
    int m = idx >> 11;
    int c = idx & 2047;
    int t = m & (TT-1);
    int d = c & (DD-1);
    int dm = d & 63;

    float ang = (float)t * g_invfreq[dm];
    float sn, cs;
    sincosf(ang, &sn, &cs);

    size_t base = (size_t)m * N_QKV;
    float qv = g_qkv[base + c];
    float kv = g_qkv[base + CC + c];
    float vv = g_qkv[base + 2*CC + c];

    int c2 = (d < 64) ? (c + 64) : (c - 64);
    float sgn = (d < 64) ? -1.f : 1.f;
    float qr = g_qkv[base + c2];
    float kr = g_qkv[base + CC + c2];

    float qo = qv*cs + sgn*qr*sn;
    float ko = kv*cs + sgn*kr*sn;

    int b = m >> 11;
    int h = c >> 7;
    size_t o = (((size_t)(b*HH + h))*TT + t)*DD + d;

    g_qh[o] = __float2half(qo);
    g_kh[o] = __float2half(ko);
    g_vh[o] = __float2half(vv);
}

// ===========================================================================
// HMMA fp16 flash attention (single-precision throughout).
// BQ=128, BK=64, 8 warps x 16 q-rows, SMSP-balancing warp permutation.
// Smem: Q 32KB + 2 stages x (K 16KB + V 16KB) = 96KB.
// ===========================================================================
#define AQ 128
#define AK 64
#define SM_Q 32768
#define STG_SZ 32768
#define ATT_SMEM (SM_Q + 2*STG_SZ)   // 98304

__global__ __launch_bounds__(256, 1)
void attn_hmma_kernel()
{
    extern __shared__ char sm[];
    const uint32_t sb = smem_u32(sm);
    const int tid = threadIdx.x, wid = tid >> 5, lane = tid & 31;

    const int qt  = (TT/AQ - 1) - blockIdx.x;
    const int bh  = blockIdx.y;
    const int qt0 = qt * AQ;
    const size_t base = (size_t)bh * TT * DD;
    const __half *qhp = g_qh + base;
    const __half *khp = g_kh + base;
    const __half *vhp = g_vh + base;

    #pragma unroll
    for (int e = 0; e < 8; e++) {
        int idx = e*256 + tid;              // 0..2047
        int r   = (idx >> 4) & 127;
        int ug  = idx & 15;
        int h2 = ug >> 3, u = ug & 7;
        uint32_t dst = sb + h2*16384 + r*128 + ((u ^ (r & 7))*16);
        CP_ASYNC16(dst, qhp + (size_t)(qt0 + r)*DD + ug*8);
    }

    const int nch = 2*qt + 2;

    auto load_stage = [&](int buf, int j0) {
        uint32_t stg = sb + SM_Q + buf*STG_SZ;
        #pragma unroll
        for (int e = 0; e < 4; e++) {       // K
            int idx = e*256 + tid;
            int r   = (idx >> 4) & 63;
            int ug  = idx & 15;
            int h2 = ug >> 3, u = ug & 7;
            uint32_t dst = stg + h2*8192 + r*128 + ((u ^ (r & 7))*16);
            CP_ASYNC16(dst, khp + (size_t)(j0 + r)*DD + ug*8);
        }
        #pragma unroll
        for (int e = 0; e < 4; e++) {       // V
            int idx = e*256 + tid;
            int r   = (idx >> 4) & 63;
            int ug  = idx & 15;
            int h2 = ug >> 3, u = ug & 7;
            uint32_t dst = stg + 16384 + h2*8192 + r*128 + ((u ^ (r & 7))*16);
            CP_ASYNC16(dst, vhp + (size_t)(j0 + r)*DD + ug*8);
        }
    };

    load_stage(0, 0);
    CP_COMMIT();
    if (nch > 1) { load_stage(1, AK); CP_COMMIT(); }

    const int rowblk = (wid < 4) ? wid : (11 - wid);
    const int wrow0 = rowblk * 16;
    const int gq0 = qt0 + wrow0;

    float yac[16][4];
    #pragma unroll
    for (int nf = 0; nf < 16; nf++)
        #pragma unroll
        for (int e = 0; e < 4; e++) yac[nf][e] = 0.f;
    float mi[2] = {-1e30f, -1e30f}, li[2] = {0.f, 0.f};

    const float scale = 0.08838834764831845f;

    for (int c = 0; c < nch; c++) {
        const int j0 = c * AK;
        if (c + 1 < nch) { CP_WAIT(1); } else { CP_WAIT(0); }
        __syncthreads();

        const uint32_t stg = sb + SM_Q + (c & 1)*STG_SZ;

        if (j0 < gq0 + 16) {
            float sa[8][4];
            #pragma unroll
            for (int nf = 0; nf < 8; nf++)
                #pragma unroll
                for (int e = 0; e < 4; e++) sa[nf][e] = 0.f;

            #pragma unroll
            for (int kh2 = 0; kh2 < 2; kh2++) {
                uint32_t qb = sb + kh2*16384;
                uint32_t kb = stg + kh2*8192;
                #pragma unroll
                for (int ks = 0; ks < 4; ks++) {
                    int ar = wrow0 + (lane & 7) + ((lane >> 3) & 1)*8;
                    int au = ks*2 + (lane >> 4);
                    uint32_t aoff = ar*128 + ((au ^ (ar & 7))*16);
                    uint32_t Qh4[4];
                    ldsm4(Qh4, qb + aoff);
                    int br_ = ((lane >> 4) & 1)*8 + (lane & 7);
                    int bu  = ks*2 + ((lane >> 3) & 1);
                    #pragma unroll
                    for (int nb = 0; nb < 4; nb++) {
                        int r = br_ + nb*16;
                        uint32_t boff = r*128 + ((bu ^ (r & 7))*16);
                        uint32_t Kh4[4];
                        ldsm4(Kh4, kb + boff);
                        mma_f16(sa[2*nb],   Qh4, Kh4);
                        mma_f16(sa[2*nb+1], Qh4, Kh4+2);
                    }
                }
            }

            #pragma unroll
            for (int nf = 0; nf < 8; nf++)
                #pragma unroll
                for (int e = 0; e < 4; e++) sa[nf][e] *= scale;
            if (j0 + 63 > gq0) {
                #pragma unroll
                for (int nf = 0; nf < 8; nf++)
                    #pragma unroll
                    for (int e = 0; e < 4; e++) {
                        int row = gq0 + (lane >> 2) + (e >> 1)*8;
                        int col = j0 + nf*8 + 2*(lane & 3) + (e & 1);
                        if (col > row) sa[nf][e] = -1e30f;
                    }
            }

            #pragma unroll
            for (int rh = 0; rh < 2; rh++) {
                float m = -1e30f;
                #pragma unroll
                for (int nf = 0; nf < 8; nf++)
                    m = fmaxf(m, fmaxf(sa[nf][rh*2], sa[nf][rh*2+1]));
                m = fmaxf(m, __shfl_xor_sync(0xffffffffu, m, 1));
                m = fmaxf(m, __shfl_xor_sync(0xffffffffu, m, 2));
                float mnew = fmaxf(mi[rh], m);
                float corr = __expf(mi[rh] - mnew);
                float rs = 0.f;
                #pragma unroll
                for (int nf = 0; nf < 8; nf++) {
                    float p0 = __expf(sa[nf][rh*2]   - mnew);
                    float p1 = __expf(sa[nf][rh*2+1] - mnew);
                    sa[nf][rh*2] = p0; sa[nf][rh*2+1] = p1;
                    rs += p0 + p1;
                }
                rs += __shfl_xor_sync(0xffffffffu, rs, 1);
                rs += __shfl_xor_sync(0xffffffffu, rs, 2);
                li[rh] = li[rh]*corr + rs;
                mi[rh] = mnew;
                #pragma unroll
                for (int nf = 0; nf < 16; nf++) {
                    yac[nf][rh*2]   *= corr;
                    yac[nf][rh*2+1] *= corr;
                }
            }

            uint32_t pH[4][4];
            #pragma unroll
            for (int j = 0; j < 4; j++) {
                #pragma unroll
                for (int q = 0; q < 4; q++) {
                    int f = 2*j + (q >> 1);
                    int o = (q & 1)*2;
                    __half2 hp;
                    hp.x = __float2half(sa[f][o]);
                    hp.y = __float2half(sa[f][o+1]);
                    pH[j][q] = *(uint32_t*)&hp;
                }
            }

            const uint32_t vb = stg + 16384;
            #pragma unroll
            for (int ks = 0; ks < 4; ks++) {
                #pragma unroll
                for (int db = 0; db < 8; db++) {
                    int m4 = lane >> 3;
                    int j = ks*16 + (m4 & 1)*8 + (lane & 7);
                    int un = (db & 3)*2 + (m4 >> 1);
                    uint32_t off = (db >> 2)*8192 + j*128 + ((un ^ (j & 7))*16);
                    uint32_t Vh4[4];
                    ldsm4t(Vh4, vb + off);
                    mma_f16(yac[db*2],   pH[ks], Vh4);
                    mma_f16(yac[db*2+1], pH[ks], Vh4+2);
                }
            }
        }

        __syncthreads();
        if (c + 2 < nch) { load_stage(c & 1, (c+2)*AK); CP_COMMIT(); }
    }

    // epilogue: normalize, write fp16 [B,T,C]
    const int b = bh >> 4, h = bh & 15;
    #pragma unroll
    for (int rh = 0; rh < 2; rh++) {
        float inv = 1.f / li[rh];
        int t = gq0 + (lane >> 2) + rh*8;
        size_t rowo = ((size_t)(b*TT + t))*CC + h*DD;
        #pragma unroll
        for (int nf = 0; nf < 16; nf++) {
            int col = nf*8 + 2*(lane & 3);
            __half2 hp;
            hp.x = __float2half(yac[nf][rh*2]*inv);
            hp.y = __float2half(yac[nf][rh*2+1]*inv);
            *(__half2*)(g_yh + rowo + col) = hp;
        }
    }
}

// ===========================================================================
extern "C" void kernel_launch(void* const* d_in, const int* in_sizes, int n_in,
                              void* d_out, int out_size)
{
    const float* x     = (const float*)d_in[0];
    const float* w_qkv = (const float*)d_in[1];
    const float* w_out = (const float*)d_in[2];
    float* out = (float*)d_out;

    float *qkv_ptr;
    __half *xh, *yh, *wqh, *woh;
    cudaGetSymbolAddress((void**)&qkv_ptr, g_qkv);
    cudaGetSymbolAddress((void**)&xh, g_xh);
    cudaGetSymbolAddress((void**)&yh, g_yh);
    cudaGetSymbolAddress((void**)&wqh, g_wqt_h);
    cudaGetSymbolAddress((void**)&woh, g_wot_h);

    static int attr_set = 0;
    if (!attr_set) {
        cudaFuncSetAttribute(gemm_hmma_kernel,
                             cudaFuncAttributeMaxDynamicSharedMemorySize, GH_SMEM);
        cudaFuncSetAttribute(attn_hmma_kernel,
                             cudaFuncAttributeMaxDynamicSharedMemorySize, ATT_SMEM);
        attr_set = 1;
    }

    init_invfreq_kernel<<<1, 64>>>();

    convert_kernel<<<(MM*CC + 255)/256, 256>>>(x, xh, MM*CC);
    transpose_split_kernel<<<dim3(N_QKV/32, CC/32), 256>>>(w_qkv, wqh, CC, N_QKV);
    transpose_split_kernel<<<dim3(CC/32, CC/32), 256>>>(w_out, woh, CC, CC);

    // qkv = x @ w_qkv
    gemm_hmma_kernel<<<dim3(N_QKV/128, MM/128), 256, GH_SMEM>>>(
        xh, wqh, qkv_ptr, MM, N_QKV, CC);

    // RoPE + convert to fp16 [B,H,T,D]
    rope_split_kernel<<<(MM*CC)/256, 256>>>();

    // fp16 flash attention -> yh [B,T,C]
    attn_hmma_kernel<<<dim3(TT/AQ, BB*HH), 256, ATT_SMEM>>>();

    // out = y @ w_out
    gemm_hmma_kernel<<<dim3(CC/128, MM/128), 256, GH_SMEM>>>(
        yh, woh, out, MM, CC, CC);
}

// round 12
// speedup vs baseline: 1.8334x; 1.0249x over previous
#include <cuda_runtime.h>
#include <cuda_fp16.h>
#include <cstdint>
#include <math.h>

// Problem constants
#define BB 2
#define TT 2048
#define CC 2048
#define HH 16
#define DD 128
#define MM (BB*TT)          // 4096
#define N_QKV (3*CC)        // 6144

// Scratch (static device globals; no runtime allocation allowed)
__device__ float g_invfreq[DD/2];

// fp16 operands
__device__ __half g_qkv16[(size_t)MM * N_QKV];   // GEMM1 out [M, 3C] fp16
__device__ __half g_xh[(size_t)MM * CC];
__device__ __half g_yh[(size_t)MM * CC];         // attention out [B,T,C]
__device__ __half g_wqt_h[(size_t)N_QKV * CC];   // w_qkv^T [N,K]
__device__ __half g_wot_h[(size_t)CC * CC];      // w_out^T
__device__ __half g_qh[(size_t)MM * CC];         // [B,H,T,D]
__device__ __half g_kh[(size_t)MM * CC];
__device__ __half g_vh[(size_t)MM * CC];

// ===========================================================================
__device__ __forceinline__ uint32_t smem_u32(const void* p) {
    uint32_t a;
    asm("{ .reg .u64 t; cvta.to.shared.u64 t, %1; cvt.u32.u64 %0, t; }"
        : "=r"(a) : "l"(p));
    return a;
}
#define CP_ASYNC16(dst, src) \
    asm volatile("cp.async.cg.shared.global [%0], [%1], 16;" :: "r"(dst), "l"(src))
#define CP_COMMIT() asm volatile("cp.async.commit_group;" ::: "memory")
#define CP_WAIT(n)  asm volatile("cp.async.wait_group %0;" :: "n"(n) : "memory")

__device__ __forceinline__ void ldsm4(uint32_t* r, uint32_t addr) {
    asm volatile("ldmatrix.sync.aligned.m8n8.x4.shared.b16 {%0,%1,%2,%3}, [%4];"
        : "=r"(r[0]), "=r"(r[1]), "=r"(r[2]), "=r"(r[3]) : "r"(addr));
}
__device__ __forceinline__ void ldsm4t(uint32_t* r, uint32_t addr) {
    asm volatile("ldmatrix.sync.aligned.m8n8.x4.trans.shared.b16 {%0,%1,%2,%3}, [%4];"
        : "=r"(r[0]), "=r"(r[1]), "=r"(r[2]), "=r"(r[3]) : "r"(addr));
}
__device__ __forceinline__ void mma_f16(float* d, const uint32_t* a, const uint32_t* b) {
    asm volatile("mma.sync.aligned.m16n8k16.row.col.f32.f16.f16.f32 "
        "{%0,%1,%2,%3}, {%4,%5,%6,%7}, {%8,%9}, {%0,%1,%2,%3};"
        : "+f"(d[0]), "+f"(d[1]), "+f"(d[2]), "+f"(d[3])
        : "r"(a[0]), "r"(a[1]), "r"(a[2]), "r"(a[3]), "r"(b[0]), "r"(b[1]));
}

// ===========================================================================
__global__ void init_invfreq_kernel() {
    int i = threadIdx.x;
    if (i < DD/2) {
        double e = (double)(2*i) / (double)DD;
        g_invfreq[i] = (float)(1.0 / pow(10000.0, e));
    }
}

// fp32 -> fp16
__global__ __launch_bounds__(256)
void convert_kernel(const float* __restrict__ src,
                    __half* __restrict__ dst, int n)
{
    int i = blockIdx.x * 256 + threadIdx.x;
    if (i < n) dst[i] = __float2half(src[i]);
}

// W[K][N] -> Th[N][K] transposed fp16
__global__ __launch_bounds__(256)
void transpose_split_kernel(const float* __restrict__ W,
                            __half* __restrict__ Th, int K, int N)
{
    __shared__ float tile[32][33];
    int n0 = blockIdx.x * 32, k0 = blockIdx.y * 32;
    int tx = threadIdx.x & 31, ty = threadIdx.x >> 5;
    #pragma unroll
    for (int r = 0; r < 4; r++)
        tile[ty + r*8][tx] = W[(size_t)(k0 + ty + r*8)*N + n0 + tx];
    __syncthreads();
    #pragma unroll
    for (int r = 0; r < 4; r++) {
        float v = tile[tx][ty + r*8];
        Th[(size_t)(n0 + ty + r*8)*K + k0 + tx] = __float2half(v);
    }
}

// ===========================================================================
// HMMA fp16 GEMM: C = Ah[M,K] . Bh[N,K]^T  (single product)
// CTA tile 128x128, 256 threads (8 warps 2x4), warp tile 64x32, KC=64.
// Stage: A(16K) + B(16K) = 32KB; double-buffered = 64KB. 2 CTAs/SM.
// Templated output type: fp32 (final out) or fp16 (qkv intermediate).
// ===========================================================================
#define KC 64
#define GT_B 16384
#define STAGE_B (2*GT_B)
#define GH_SMEM (2*STAGE_B)   // 65536

template<typename OT>
__global__ __launch_bounds__(256, 2)
void gemm_hmma_kernel(const __half* __restrict__ Ah,
                      const __half* __restrict__ Bh,
                      OT* __restrict__ C, int M, int N, int K)
{
    extern __shared__ char sm[];
    const uint32_t sbase = smem_u32(sm);

    const int tid  = threadIdx.x;
    const int wid  = tid >> 5;
    const int lane = tid & 31;
    const int wm = wid >> 2;
    const int wn = wid & 3;
    const int bm = blockIdx.y * 128;
    const int bn = blockIdx.x * 128;

    const __half* srcs[2] = { Ah + (size_t)bm*K, Bh + (size_t)bn*K };

    const int aRowB = wm*64 + (lane & 7) + ((lane >> 3) & 1)*8;
    const int aCH   = lane >> 4;
    const int bRowB = wn*32 + ((lane >> 4) & 1)*8 + (lane & 7);
    const int bCH   = (lane >> 3) & 1;

    float acc[4][4][4];
    #pragma unroll
    for (int mt = 0; mt < 4; mt++)
        #pragma unroll
        for (int nt = 0; nt < 4; nt++)
            #pragma unroll
            for (int e = 0; e < 4; e++) acc[mt][nt][e] = 0.f;

    auto load_stage = [&](int buf, int kc) {
        uint32_t stg = sbase + buf*STAGE_B;
        #pragma unroll
        for (int t = 0; t < 2; t++) {
            const __half* sp = srcs[t] + kc*KC;
            uint32_t db = stg + t*GT_B;
            #pragma unroll
            for (int e = 0; e < 4; e++) {
                int idx = e*256 + tid;
                int row = idx >> 3, u = idx & 7;
                uint32_t d = db + row*128 + ((u ^ (row & 7))*16);
                CP_ASYNC16(d, sp + (size_t)row*K + u*8);
            }
        }
    };

    const int nch = K / KC;
    load_stage(0, 0);
    CP_COMMIT();

    for (int c = 0; c < nch; c++) {
        if (c + 1 < nch) {
            load_stage((c+1) & 1, c+1);
            CP_COMMIT();
            CP_WAIT(1);
        } else {
            CP_WAIT(0);
        }
        __syncthreads();

        const uint32_t stg = sbase + (c & 1)*STAGE_B;

        #pragma unroll
        for (int ks = 0; ks < 4; ks++) {
            uint32_t ah[4][4], bh[2][4];
            #pragma unroll
            for (int mt = 0; mt < 4; mt++) {
                int r = aRowB + mt*16;
                uint32_t off = r*128 + (((ks*2 + aCH) ^ (r & 7))*16);
                ldsm4(ah[mt], stg + off);
            }
            #pragma unroll
            for (int nt2 = 0; nt2 < 2; nt2++) {
                int r = bRowB + nt2*16;
                uint32_t off = r*128 + (((ks*2 + bCH) ^ (r & 7))*16);
                ldsm4(bh[nt2], stg + GT_B + off);
            }
            #pragma unroll
            for (int mt = 0; mt < 4; mt++) {
                #pragma unroll
                for (int nt = 0; nt < 4; nt++) {
                    const uint32_t* bhp = &bh[nt >> 1][(nt & 1)*2];
                    mma_f16(acc[mt][nt], ah[mt], bhp);
                }
            }
        }
        __syncthreads();
    }

    #pragma unroll
    for (int mt = 0; mt < 4; mt++) {
        #pragma unroll
        for (int nt = 0; nt < 4; nt++) {
            int r0 = bm + wm*64 + mt*16 + (lane >> 2);
            int c0 = bn + wn*32 + nt*8 + (lane & 3)*2;
            if (sizeof(OT) == 4) {
                *(float2*)((float*)C + (size_t)r0*N + c0) =
                    make_float2(acc[mt][nt][0], acc[mt][nt][1]);
                *(float2*)((float*)C + (size_t)(r0+8)*N + c0) =
                    make_float2(acc[mt][nt][2], acc[mt][nt][3]);
            } else {
                *(__half2*)((__half*)C + (size_t)r0*N + c0) =
                    __floats2half2_rn(acc[mt][nt][0], acc[mt][nt][1]);
                *(__half2*)((__half*)C + (size_t)(r0+8)*N + c0) =
                    __floats2half2_rn(acc[mt][nt][2], acc[mt][nt][3]);
            }
        }
    }
}

// ===========================================================================
// RoPE pair-wise: thread owns (d, d+1) in lower half + partners (d+64, d+65),
// for q, k, v. Each qkv element is read exactly once; one sincos pair serves
// 8 rotated outputs. Reads fp16 qkv, writes fp16 [B,H,T,D].
// Grid: MM * 512 threads (512 = 16 heads x 32 d-pairs).
// ===========================================================================
__global__ __launch_bounds__(256)
void rope_kernel()
{
    int idx = blockIdx.x * 256 + threadIdx.x;   // 0 .. MM*512-1
    int m  = idx >> 9;
    int r  = idx & 511;
    int h  = r >> 5;
    int d  = (r & 31) * 2;      // 0..62 (lower half)
    int t  = m & (TT-1);
    int b  = m >> 11;

    float sn0, cs0, sn1, cs1;
    sincosf((float)t * g_invfreq[d],   &sn0, &cs0);
    sincosf((float)t * g_invfreq[d+1], &sn1, &cs1);

    const __half2* qkv = (const __half2*)(g_qkv16 + (size_t)m * N_QKV);
    int cl = (h*DD + d) >> 1;          // half2 index, lower
    int cu = cl + 32;                  // +64 elements

    // q
    {
        float2 lo = __half22float2(qkv[cl]);
        float2 up = __half22float2(qkv[cu]);
        size_t o = (((size_t)(b*HH + h))*TT + t)*DD + d;
        *(__half2*)(g_qh + o)      = __floats2half2_rn(lo.x*cs0 - up.x*sn0,
                                                       lo.y*cs1 - up.y*sn1);
        *(__half2*)(g_qh + o + 64) = __floats2half2_rn(up.x*cs0 + lo.x*sn0,
                                                       up.y*cs1 + lo.y*sn1);
    }
    // k
    {
        float2 lo = __half22float2(qkv[cl + CC/2]);
        float2 up = __half22float2(qkv[cu + CC/2]);
        size_t o = (((size_t)(b*HH + h))*TT + t)*DD + d;
        *(__half2*)(g_kh + o)      = __floats2half2_rn(lo.x*cs0 - up.x*sn0,
                                                       lo.y*cs1 - up.y*sn1);
        *(__half2*)(g_kh + o + 64) = __floats2half2_rn(up.x*cs0 + lo.x*sn0,
                                                       up.y*cs1 + lo.y*sn1);
    }
    // v (pass-through)
    {
        size_t o = (((size_t)(b*HH + h))*TT + t)*DD + d;
        *(__half2*)(g_vh + o)      = qkv[cl + CC];
        *(__half2*)(g_vh + o + 64) = qkv[cu + CC];
    }
}

// ===========================================================================
// HMMA fp16 flash attention (single-precision throughout).
// BQ=128, BK=64, 8 warps x 16 q-rows, SMSP-balancing warp permutation.
// Smem: Q 32KB + 2 stages x (K 16KB + V 16KB) = 96KB.
// ===========================================================================
#define AQ 128
#define AK 64
#define SM_Q 32768
#define STG_SZ 32768
#define ATT_SMEM (SM_Q + 2*STG_SZ)   // 98304

__global__ __launch_bounds__(256, 1)
void attn_hmma_kernel()
{
    extern __shared__ char sm[];
    const uint32_t sb = smem_u32(sm);
    const int tid = threadIdx.x, wid = tid >> 5, lane = tid & 31;

    const int qt  = (TT/AQ - 1) - blockIdx.x;
    const int bh  = blockIdx.y;
    const int qt0 = qt * AQ;
    const size_t base = (size_t)bh * TT * DD;
    const __half *qhp = g_qh + base;
    const __half *khp = g_kh + base;
    const __half *vhp = g_vh + base;

    #pragma unroll
    for (int e = 0; e < 8; e++) {
        int idx = e*256 + tid;              // 0..2047
        int r   = (idx >> 4) & 127;
        int ug  = idx & 15;
        int h2 = ug >> 3, u = ug & 7;
        uint32_t dst = sb + h2*16384 + r*128 + ((u ^ (r & 7))*16);
        CP_ASYNC16(dst, qhp + (size_t)(qt0 + r)*DD + ug*8);
    }

    const int nch = 2*qt + 2;

    auto load_stage = [&](int buf, int j0) {
        uint32_t stg = sb + SM_Q + buf*STG_SZ;
        #pragma unroll
        for (int e = 0; e < 4; e++) {       // K
            int idx = e*256 + tid;
            int r   = (idx >> 4) & 63;
            int ug  = idx & 15;
            int h2 = ug >> 3, u = ug & 7;
            uint32_t dst = stg + h2*8192 + r*128 + ((u ^ (r & 7))*16);
            CP_ASYNC16(dst, khp + (size_t)(j0 + r)*DD + ug*8);
        }
        #pragma unroll
        for (int e = 0; e < 4; e++) {       // V
            int idx = e*256 + tid;
            int r   = (idx >> 4) & 63;
            int ug  = idx & 15;
            int h2 = ug >> 3, u = ug & 7;
            uint32_t dst = stg + 16384 + h2*8192 + r*128 + ((u ^ (r & 7))*16);
            CP_ASYNC16(dst, vhp + (size_t)(j0 + r)*DD + ug*8);
        }
    };

    load_stage(0, 0);
    CP_COMMIT();
    if (nch > 1) { load_stage(1, AK); CP_COMMIT(); }

    const int rowblk = (wid < 4) ? wid : (11 - wid);
    const int wrow0 = rowblk * 16;
    const int gq0 = qt0 + wrow0;

    float yac[16][4];
    #pragma unroll
    for (int nf = 0; nf < 16; nf++)
        #pragma unroll
        for (int e = 0; e < 4; e++) yac[nf][e] = 0.f;
    float mi[2] = {-1e30f, -1e30f}, li[2] = {0.f, 0.f};

    const float scale = 0.08838834764831845f;

    for (int c = 0; c < nch; c++) {
        const int j0 = c * AK;
        if (c + 1 < nch) { CP_WAIT(1); } else { CP_WAIT(0); }
        __syncthreads();

        const uint32_t stg = sb + SM_Q + (c & 1)*STG_SZ;

        if (j0 < gq0 + 16) {
            float sa[8][4];
            #pragma unroll
            for (int nf = 0; nf < 8; nf++)
                #pragma unroll
                for (int e = 0; e < 4; e++) sa[nf][e] = 0.f;

            #pragma unroll
            for (int kh2 = 0; kh2 < 2; kh2++) {
                uint32_t qb = sb + kh2*16384;
                uint32_t kb = stg + kh2*8192;
                #pragma unroll
                for (int ks = 0; ks < 4; ks++) {
                    int ar = wrow0 + (lane & 7) + ((lane >> 3) & 1)*8;
                    int au = ks*2 + (lane >> 4);
                    uint32_t aoff = ar*128 + ((au ^ (ar & 7))*16);
                    uint32_t Qh4[4];
                    ldsm4(Qh4, qb + aoff);
                    int br_ = ((lane >> 4) & 1)*8 + (lane & 7);
                    int bu  = ks*2 + ((lane >> 3) & 1);
                    #pragma unroll
                    for (int nb = 0; nb < 4; nb++) {
                        int r = br_ + nb*16;
                        uint32_t boff = r*128 + ((bu ^ (r & 7))*16);
                        uint32_t Kh4[4];
                        ldsm4(Kh4, kb + boff);
                        mma_f16(sa[2*nb],   Qh4, Kh4);
                        mma_f16(sa[2*nb+1], Qh4, Kh4+2);
                    }
                }
            }

            #pragma unroll
            for (int nf = 0; nf < 8; nf++)
                #pragma unroll
                for (int e = 0; e < 4; e++) sa[nf][e] *= scale;
            if (j0 + 63 > gq0) {
                #pragma unroll
                for (int nf = 0; nf < 8; nf++)
                    #pragma unroll
                    for (int e = 0; e < 4; e++) {
                        int row = gq0 + (lane >> 2) + (e >> 1)*8;
                        int col = j0 + nf*8 + 2*(lane & 3) + (e & 1);
                        if (col > row) sa[nf][e] = -1e30f;
                    }
            }

            #pragma unroll
            for (int rh = 0; rh < 2; rh++) {
                float m = -1e30f;
                #pragma unroll
                for (int nf = 0; nf < 8; nf++)
                    m = fmaxf(m, fmaxf(sa[nf][rh*2], sa[nf][rh*2+1]));
                m = fmaxf(m, __shfl_xor_sync(0xffffffffu, m, 1));
                m = fmaxf(m, __shfl_xor_sync(0xffffffffu, m, 2));
                float mnew = fmaxf(mi[rh], m);
                float corr = __expf(mi[rh] - mnew);
                float rs = 0.f;
                #pragma unroll
                for (int nf = 0; nf < 8; nf++) {
                    float p0 = __expf(sa[nf][rh*2]   - mnew);
                    float p1 = __expf(sa[nf][rh*2+1] - mnew);
                    sa[nf][rh*2] = p0; sa[nf][rh*2+1] = p1;
                    rs += p0 + p1;
                }
                rs += __shfl_xor_sync(0xffffffffu, rs, 1);
                rs += __shfl_xor_sync(0xffffffffu, rs, 2);
                li[rh] = li[rh]*corr + rs;
                mi[rh] = mnew;
                #pragma unroll
                for (int nf = 0; nf < 16; nf++) {
                    yac[nf][rh*2]   *= corr;
                    yac[nf][rh*2+1] *= corr;
                }
            }

            uint32_t pH[4][4];
            #pragma unroll
            for (int j = 0; j < 4; j++) {
                #pragma unroll
                for (int q = 0; q < 4; q++) {
                    int f = 2*j + (q >> 1);
                    int o = (q & 1)*2;
                    __half2 hp;
                    hp.x = __float2half(sa[f][o]);
                    hp.y = __float2half(sa[f][o+1]);
                    pH[j][q] = *(uint32_t*)&hp;
                }
            }

            const uint32_t vb = stg + 16384;
            #pragma unroll
            for (int ks = 0; ks < 4; ks++) {
                #pragma unroll
                for (int db = 0; db < 8; db++) {
                    int m4 = lane >> 3;
                    int j = ks*16 + (m4 & 1)*8 + (lane & 7);
                    int un = (db & 3)*2 + (m4 >> 1);
                    uint32_t off = (db >> 2)*8192 + j*128 + ((un ^ (j & 7))*16);
                    uint32_t Vh4[4];
                    ldsm4t(Vh4, vb + off);
                    mma_f16(yac[db*2],   pH[ks], Vh4);
                    mma_f16(yac[db*2+1], pH[ks], Vh4+2);
                }
            }
        }

        __syncthreads();
        if (c + 2 < nch) { load_stage(c & 1, (c+2)*AK); CP_COMMIT(); }
    }

    // epilogue: normalize, write fp16 [B,T,C]
    const int b = bh >> 4, h = bh & 15;
    #pragma unroll
    for (int rh = 0; rh < 2; rh++) {
        float inv = 1.f / li[rh];
        int t = gq0 + (lane >> 2) + rh*8;
        size_t rowo = ((size_t)(b*TT + t))*CC + h*DD;
        #pragma unroll
        for (int nf = 0; nf < 16; nf++) {
            int col = nf*8 + 2*(lane & 3);
            __half2 hp;
            hp.x = __float2half(yac[nf][rh*2]*inv);
            hp.y = __float2half(yac[nf][rh*2+1]*inv);
            *(__half2*)(g_yh + rowo + col) = hp;
        }
    }
}

// ===========================================================================
extern "C" void kernel_launch(void* const* d_in, const int* in_sizes, int n_in,
                              void* d_out, int out_size)
{
    const float* x     = (const float*)d_in[0];
    const float* w_qkv = (const float*)d_in[1];
    const float* w_out = (const float*)d_in[2];
    float* out = (float*)d_out;

    __half *qkv16, *xh, *yh, *wqh, *woh;
    cudaGetSymbolAddress((void**)&qkv16, g_qkv16);
    cudaGetSymbolAddress((void**)&xh, g_xh);
    cudaGetSymbolAddress((void**)&yh, g_yh);
    cudaGetSymbolAddress((void**)&wqh, g_wqt_h);
    cudaGetSymbolAddress((void**)&woh, g_wot_h);

    static int attr_set = 0;
    if (!attr_set) {
        cudaFuncSetAttribute(gemm_hmma_kernel<float>,
                             cudaFuncAttributeMaxDynamicSharedMemorySize, GH_SMEM);
        cudaFuncSetAttribute(gemm_hmma_kernel<__half>,
                             cudaFuncAttributeMaxDynamicSharedMemorySize, GH_SMEM);
        cudaFuncSetAttribute(attn_hmma_kernel,
                             cudaFuncAttributeMaxDynamicSharedMemorySize, ATT_SMEM);
        attr_set = 1;
    }

    init_invfreq_kernel<<<1, 64>>>();

    convert_kernel<<<(MM*CC + 255)/256, 256>>>(x, xh, MM*CC);
    transpose_split_kernel<<<dim3(N_QKV/32, CC/32), 256>>>(w_qkv, wqh, CC, N_QKV);
    transpose_split_kernel<<<dim3(CC/32, CC/32), 256>>>(w_out, woh, CC, CC);

    // qkv = x @ w_qkv  (fp16 output)
    gemm_hmma_kernel<__half><<<dim3(N_QKV/128, MM/128), 256, GH_SMEM>>>(
        xh, wqh, qkv16, MM, N_QKV, CC);

    // RoPE pair-wise -> q/k/v fp16 [B,H,T,D]
    rope_kernel<<<(MM*512)/256, 256>>>();

    // fp16 flash attention -> yh [B,T,C]
    attn_hmma_kernel<<<dim3(TT/AQ, BB*HH), 256, ATT_SMEM>>>();

    // out = y @ w_out  (fp32 output)
    gemm_hmma_kernel<float><<<dim3(CC/128, MM/128), 256, GH_SMEM>>>(
        yh, woh, out, MM, CC, CC);
}

// round 13
// speedup vs baseline: 1.8404x; 1.0038x over previous
#include <cuda_runtime.h>
#include <cuda_fp16.h>
#include <cstdint>
#include <math.h>

// Problem constants
#define BB 2
#define TT 2048
#define CC 2048
#define HH 16
#define DD 128
#define MM (BB*TT)          // 4096
#define N_QKV (3*CC)        // 6144

// Scratch (static device globals; no runtime allocation allowed)
__device__ float g_invfreq[DD/2];

// fp16 operands
__device__ __half g_qkv16[(size_t)MM * N_QKV];   // GEMM1 out [M, 3C] fp16
__device__ __half g_xh[(size_t)MM * CC];
__device__ __half g_yh[(size_t)MM * CC];         // attention out [B,T,C]
__device__ __half g_wqt_h[(size_t)N_QKV * CC];   // w_qkv^T [N,K]
__device__ __half g_wot_h[(size_t)CC * CC];      // w_out^T
__device__ __half g_qh[(size_t)MM * CC];         // [B,H,T,D]
__device__ __half g_kh[(size_t)MM * CC];
__device__ __half g_vh[(size_t)MM * CC];

// ===========================================================================
__device__ __forceinline__ uint32_t smem_u32(const void* p) {
    uint32_t a;
    asm("{ .reg .u64 t; cvta.to.shared.u64 t, %1; cvt.u32.u64 %0, t; }"
        : "=r"(a) : "l"(p));
    return a;
}
#define CP_ASYNC16(dst, src) \
    asm volatile("cp.async.cg.shared.global [%0], [%1], 16;" :: "r"(dst), "l"(src))
#define CP_COMMIT() asm volatile("cp.async.commit_group;" ::: "memory")
#define CP_WAIT(n)  asm volatile("cp.async.wait_group %0;" :: "n"(n) : "memory")

__device__ __forceinline__ void ldsm4(uint32_t* r, uint32_t addr) {
    asm volatile("ldmatrix.sync.aligned.m8n8.x4.shared.b16 {%0,%1,%2,%3}, [%4];"
        : "=r"(r[0]), "=r"(r[1]), "=r"(r[2]), "=r"(r[3]) : "r"(addr));
}
__device__ __forceinline__ void ldsm4t(uint32_t* r, uint32_t addr) {
    asm volatile("ldmatrix.sync.aligned.m8n8.x4.trans.shared.b16 {%0,%1,%2,%3}, [%4];"
        : "=r"(r[0]), "=r"(r[1]), "=r"(r[2]), "=r"(r[3]) : "r"(addr));
}
__device__ __forceinline__ void mma_f16(float* d, const uint32_t* a, const uint32_t* b) {
    asm volatile("mma.sync.aligned.m16n8k16.row.col.f32.f16.f16.f32 "
        "{%0,%1,%2,%3}, {%4,%5,%6,%7}, {%8,%9}, {%0,%1,%2,%3};"
        : "+f"(d[0]), "+f"(d[1]), "+f"(d[2]), "+f"(d[3])
        : "r"(a[0]), "r"(a[1]), "r"(a[2]), "r"(a[3]), "r"(b[0]), "r"(b[1]));
}

// ===========================================================================
__global__ void init_invfreq_kernel() {
    int i = threadIdx.x;
    if (i < DD/2) {
        double e = (double)(2*i) / (double)DD;
        g_invfreq[i] = (float)(1.0 / pow(10000.0, e));
    }
}

__global__ __launch_bounds__(256)
void convert_kernel(const float* __restrict__ src,
                    __half* __restrict__ dst, int n)
{
    int i = blockIdx.x * 256 + threadIdx.x;
    if (i < n) dst[i] = __float2half(src[i]);
}

__global__ __launch_bounds__(256)
void transpose_split_kernel(const float* __restrict__ W,
                            __half* __restrict__ Th, int K, int N)
{
    __shared__ float tile[32][33];
    int n0 = blockIdx.x * 32, k0 = blockIdx.y * 32;
    int tx = threadIdx.x & 31, ty = threadIdx.x >> 5;
    #pragma unroll
    for (int r = 0; r < 4; r++)
        tile[ty + r*8][tx] = W[(size_t)(k0 + ty + r*8)*N + n0 + tx];
    __syncthreads();
    #pragma unroll
    for (int r = 0; r < 4; r++) {
        float v = tile[tx][ty + r*8];
        Th[(size_t)(n0 + ty + r*8)*K + k0 + tx] = __float2half(v);
    }
}

// ===========================================================================
// HMMA fp16 GEMM, 3-stage cp.async pipeline.
// CTA tile 128x128, 256 threads (8 warps 2x4), warp tile 64x32, KC=64.
// Stage: A(16K)+B(16K)=32KB; 3 stages = 96KB; 2 CTAs/SM (192KB).
// ===========================================================================
#define KC 64
#define GT_B 16384
#define STAGE_B (2*GT_B)      // 32768
#define GH_SMEM (3*STAGE_B)   // 98304

template<typename OT>
__global__ __launch_bounds__(256, 2)
void gemm_hmma_kernel(const __half* __restrict__ Ah,
                      const __half* __restrict__ Bh,
                      OT* __restrict__ C, int M, int N, int K)
{
    extern __shared__ char sm[];
    const uint32_t sbase = smem_u32(sm);

    const int tid  = threadIdx.x;
    const int wid  = tid >> 5;
    const int lane = tid & 31;
    const int wm = wid >> 2;
    const int wn = wid & 3;
    const int bm = blockIdx.y * 128;
    const int bn = blockIdx.x * 128;

    const __half* srcs[2] = { Ah + (size_t)bm*K, Bh + (size_t)bn*K };

    const int aRowB = wm*64 + (lane & 7) + ((lane >> 3) & 1)*8;
    const int aCH   = lane >> 4;
    const int bRowB = wn*32 + ((lane >> 4) & 1)*8 + (lane & 7);
    const int bCH   = (lane >> 3) & 1;

    float acc[4][4][4];
    #pragma unroll
    for (int mt = 0; mt < 4; mt++)
        #pragma unroll
        for (int nt = 0; nt < 4; nt++)
            #pragma unroll
            for (int e = 0; e < 4; e++) acc[mt][nt][e] = 0.f;

    auto load_stage = [&](int buf, int kc) {
        uint32_t stg = sbase + buf*STAGE_B;
        #pragma unroll
        for (int t = 0; t < 2; t++) {
            const __half* sp = srcs[t] + kc*KC;
            uint32_t db = stg + t*GT_B;
            #pragma unroll
            for (int e = 0; e < 4; e++) {
                int idx = e*256 + tid;
                int row = idx >> 3, u = idx & 7;
                uint32_t d = db + row*128 + ((u ^ (row & 7))*16);
                CP_ASYNC16(d, sp + (size_t)row*K + u*8);
            }
        }
    };

    const int nch = K / KC;
    load_stage(0, 0);
    CP_COMMIT();
    load_stage(1, 1);
    CP_COMMIT();

    for (int c = 0; c < nch; c++) {
        // issue load for c+2 BEFORE compute of c (stage (c+2)%3 freed by
        // the end-of-compute sync of iteration c-1)
        if (c + 2 < nch) {
            load_stage((c+2) % 3, c+2);
            CP_COMMIT();
            CP_WAIT(2);
        } else if (c + 1 < nch) {
            CP_WAIT(1);
        } else {
            CP_WAIT(0);
        }
        __syncthreads();

        const uint32_t stg = sbase + (c % 3)*STAGE_B;

        #pragma unroll
        for (int ks = 0; ks < 4; ks++) {
            uint32_t ah[4][4], bh[2][4];
            #pragma unroll
            for (int mt = 0; mt < 4; mt++) {
                int r = aRowB + mt*16;
                uint32_t off = r*128 + (((ks*2 + aCH) ^ (r & 7))*16);
                ldsm4(ah[mt], stg + off);
            }
            #pragma unroll
            for (int nt2 = 0; nt2 < 2; nt2++) {
                int r = bRowB + nt2*16;
                uint32_t off = r*128 + (((ks*2 + bCH) ^ (r & 7))*16);
                ldsm4(bh[nt2], stg + GT_B + off);
            }
            #pragma unroll
            for (int mt = 0; mt < 4; mt++) {
                #pragma unroll
                for (int nt = 0; nt < 4; nt++) {
                    const uint32_t* bhp = &bh[nt >> 1][(nt & 1)*2];
                    mma_f16(acc[mt][nt], ah[mt], bhp);
                }
            }
        }
        __syncthreads();
    }

    #pragma unroll
    for (int mt = 0; mt < 4; mt++) {
        #pragma unroll
        for (int nt = 0; nt < 4; nt++) {
            int r0 = bm + wm*64 + mt*16 + (lane >> 2);
            int c0 = bn + wn*32 + nt*8 + (lane & 3)*2;
            if (sizeof(OT) == 4) {
                *(float2*)((float*)C + (size_t)r0*N + c0) =
                    make_float2(acc[mt][nt][0], acc[mt][nt][1]);
                *(float2*)((float*)C + (size_t)(r0+8)*N + c0) =
                    make_float2(acc[mt][nt][2], acc[mt][nt][3]);
            } else {
                *(__half2*)((__half*)C + (size_t)r0*N + c0) =
                    __floats2half2_rn(acc[mt][nt][0], acc[mt][nt][1]);
                *(__half2*)((__half*)C + (size_t)(r0+8)*N + c0) =
                    __floats2half2_rn(acc[mt][nt][2], acc[mt][nt][3]);
            }
        }
    }
}

// ===========================================================================
// RoPE pair-wise (unchanged from R12)
// ===========================================================================
__global__ __launch_bounds__(256)
void rope_kernel()
{
    int idx = blockIdx.x * 256 + threadIdx.x;
    int m  = idx >> 9;
    int r  = idx & 511;
    int h  = r >> 5;
    int d  = (r & 31) * 2;
    int t  = m & (TT-1);
    int b  = m >> 11;

    float sn0, cs0, sn1, cs1;
    sincosf((float)t * g_invfreq[d],   &sn0, &cs0);
    sincosf((float)t * g_invfreq[d+1], &sn1, &cs1);

    const __half2* qkv = (const __half2*)(g_qkv16 + (size_t)m * N_QKV);
    int cl = (h*DD + d) >> 1;
    int cu = cl + 32;

    {
        float2 lo = __half22float2(qkv[cl]);
        float2 up = __half22float2(qkv[cu]);
        size_t o = (((size_t)(b*HH + h))*TT + t)*DD + d;
        *(__half2*)(g_qh + o)      = __floats2half2_rn(lo.x*cs0 - up.x*sn0,
                                                       lo.y*cs1 - up.y*sn1);
        *(__half2*)(g_qh + o + 64) = __floats2half2_rn(up.x*cs0 + lo.x*sn0,
                                                       up.y*cs1 + lo.y*sn1);
    }
    {
        float2 lo = __half22float2(qkv[cl + CC/2]);
        float2 up = __half22float2(qkv[cu + CC/2]);
        size_t o = (((size_t)(b*HH + h))*TT + t)*DD + d;
        *(__half2*)(g_kh + o)      = __floats2half2_rn(lo.x*cs0 - up.x*sn0,
                                                       lo.y*cs1 - up.y*sn1);
        *(__half2*)(g_kh + o + 64) = __floats2half2_rn(up.x*cs0 + lo.x*sn0,
                                                       up.y*cs1 + lo.y*sn1);
    }
    {
        size_t o = (((size_t)(b*HH + h))*TT + t)*DD + d;
        *(__half2*)(g_vh + o)      = qkv[cl + CC];
        *(__half2*)(g_vh + o + 64) = qkv[cu + CC];
    }
}

// ===========================================================================
// HMMA fp16 flash attention, 3-stage K/V pipeline + Q-fragment hoisting.
// BQ=128, BK=64, 8 warps x 16 q-rows, SMSP-balancing warp permutation.
// Smem: Q 32KB + 3 stages x 32KB = 128KB.
// ===========================================================================
#define AQ 128
#define AK 64
#define SM_Q 32768
#define STG_SZ 32768
#define ATT_SMEM (SM_Q + 3*STG_SZ)   // 131072

__global__ __launch_bounds__(256, 1)
void attn_hmma_kernel()
{
    extern __shared__ char sm[];
    const uint32_t sb = smem_u32(sm);
    const int tid = threadIdx.x, wid = tid >> 5, lane = tid & 31;

    const int qt  = (TT/AQ - 1) - blockIdx.x;
    const int bh  = blockIdx.y;
    const int qt0 = qt * AQ;
    const size_t base = (size_t)bh * TT * DD;
    const __half *qhp = g_qh + base;
    const __half *khp = g_kh + base;
    const __half *vhp = g_vh + base;

    // Q tile into smem (group 0 along with stage 0)
    #pragma unroll
    for (int e = 0; e < 8; e++) {
        int idx = e*256 + tid;
        int r   = (idx >> 4) & 127;
        int ug  = idx & 15;
        int h2 = ug >> 3, u = ug & 7;
        uint32_t dst = sb + h2*16384 + r*128 + ((u ^ (r & 7))*16);
        CP_ASYNC16(dst, qhp + (size_t)(qt0 + r)*DD + ug*8);
    }

    const int nch = 2*qt + 2;

    auto load_stage = [&](int buf, int j0) {
        uint32_t stg = sb + SM_Q + buf*STG_SZ;
        #pragma unroll
        for (int e = 0; e < 4; e++) {       // K
            int idx = e*256 + tid;
            int r   = (idx >> 4) & 63;
            int ug  = idx & 15;
            int h2 = ug >> 3, u = ug & 7;
            uint32_t dst = stg + h2*8192 + r*128 + ((u ^ (r & 7))*16);
            CP_ASYNC16(dst, khp + (size_t)(j0 + r)*DD + ug*8);
        }
        #pragma unroll
        for (int e = 0; e < 4; e++) {       // V
            int idx = e*256 + tid;
            int r   = (idx >> 4) & 63;
            int ug  = idx & 15;
            int h2 = ug >> 3, u = ug & 7;
            uint32_t dst = stg + 16384 + h2*8192 + r*128 + ((u ^ (r & 7))*16);
            CP_ASYNC16(dst, vhp + (size_t)(j0 + r)*DD + ug*8);
        }
    };

    load_stage(0, 0);
    CP_COMMIT();
    if (nch > 1) { load_stage(1, AK); CP_COMMIT(); }

    const int rowblk = (wid < 4) ? wid : (11 - wid);
    const int wrow0 = rowblk * 16;
    const int gq0 = qt0 + wrow0;

    float yac[16][4];
    #pragma unroll
    for (int nf = 0; nf < 16; nf++)
        #pragma unroll
        for (int e = 0; e < 4; e++) yac[nf][e] = 0.f;
    float mi[2] = {-1e30f, -1e30f}, li[2] = {0.f, 0.f};

    uint32_t Qfrag[2][4][4];   // [kh2][ks][4] — hoisted Q fragments

    const float scale = 0.08838834764831845f;

    for (int c = 0; c < nch; c++) {
        const int j0 = c * AK;

        if (c + 2 < nch) {
            load_stage((c+2) % 3, (c+2)*AK);
            CP_COMMIT();
            CP_WAIT(2);
        } else if (c + 1 < nch) {
            CP_WAIT(1);
        } else {
            CP_WAIT(0);
        }
        __syncthreads();

        if (c == 0) {
            // Q ready (group 0 drained): hoist fragments into registers
            #pragma unroll
            for (int kh2 = 0; kh2 < 2; kh2++) {
                uint32_t qb = sb + kh2*16384;
                #pragma unroll
                for (int ks = 0; ks < 4; ks++) {
                    int ar = wrow0 + (lane & 7) + ((lane >> 3) & 1)*8;
                    int au = ks*2 + (lane >> 4);
                    uint32_t aoff = ar*128 + ((au ^ (ar & 7))*16);
                    ldsm4(Qfrag[kh2][ks], qb + aoff);
                }
            }
        }

        const uint32_t stg = sb + SM_Q + (c % 3)*STG_SZ;

        if (j0 < gq0 + 16) {
            float sa[8][4];
            #pragma unroll
            for (int nf = 0; nf < 8; nf++)
                #pragma unroll
                for (int e = 0; e < 4; e++) sa[nf][e] = 0.f;

            #pragma unroll
            for (int kh2 = 0; kh2 < 2; kh2++) {
                uint32_t kb = stg + kh2*8192;
                #pragma unroll
                for (int ks = 0; ks < 4; ks++) {
                    int br_ = ((lane >> 4) & 1)*8 + (lane & 7);
                    int bu  = ks*2 + ((lane >> 3) & 1);
                    #pragma unroll
                    for (int nb = 0; nb < 4; nb++) {
                        int r = br_ + nb*16;
                        uint32_t boff = r*128 + ((bu ^ (r & 7))*16);
                        uint32_t Kh4[4];
                        ldsm4(Kh4, kb + boff);
                        mma_f16(sa[2*nb],   Qfrag[kh2][ks], Kh4);
                        mma_f16(sa[2*nb+1], Qfrag[kh2][ks], Kh4+2);
                    }
                }
            }

            #pragma unroll
            for (int nf = 0; nf < 8; nf++)
                #pragma unroll
                for (int e = 0; e < 4; e++) sa[nf][e] *= scale;
            if (j0 + 63 > gq0) {
                #pragma unroll
                for (int nf = 0; nf < 8; nf++)
                    #pragma unroll
                    for (int e = 0; e < 4; e++) {
                        int row = gq0 + (lane >> 2) + (e >> 1)*8;
                        int col = j0 + nf*8 + 2*(lane & 3) + (e & 1);
                        if (col > row) sa[nf][e] = -1e30f;
                    }
            }

            #pragma unroll
            for (int rh = 0; rh < 2; rh++) {
                float m = -1e30f;
                #pragma unroll
                for (int nf = 0; nf < 8; nf++)
                    m = fmaxf(m, fmaxf(sa[nf][rh*2], sa[nf][rh*2+1]));
                m = fmaxf(m, __shfl_xor_sync(0xffffffffu, m, 1));
                m = fmaxf(m, __shfl_xor_sync(0xffffffffu, m, 2));
                float mnew = fmaxf(mi[rh], m);
                float corr = __expf(mi[rh] - mnew);
                float rs = 0.f;
                #pragma unroll
                for (int nf = 0; nf < 8; nf++) {
                    float p0 = __expf(sa[nf][rh*2]   - mnew);
                    float p1 = __expf(sa[nf][rh*2+1] - mnew);
                    sa[nf][rh*2] = p0; sa[nf][rh*2+1] = p1;
                    rs += p0 + p1;
                }
                rs += __shfl_xor_sync(0xffffffffu, rs, 1);
                rs += __shfl_xor_sync(0xffffffffu, rs, 2);
                li[rh] = li[rh]*corr + rs;
                mi[rh] = mnew;
                #pragma unroll
                for (int nf = 0; nf < 16; nf++) {
                    yac[nf][rh*2]   *= corr;
                    yac[nf][rh*2+1] *= corr;
                }
            }

            uint32_t pH[4][4];
            #pragma unroll
            for (int j = 0; j < 4; j++) {
                #pragma unroll
                for (int q = 0; q < 4; q++) {
                    int f = 2*j + (q >> 1);
                    int o = (q & 1)*2;
                    __half2 hp;
                    hp.x = __float2half(sa[f][o]);
                    hp.y = __float2half(sa[f][o+1]);
                    pH[j][q] = *(uint32_t*)&hp;
                }
            }

            const uint32_t vb = stg + 16384;
            #pragma unroll
            for (int ks = 0; ks < 4; ks++) {
                #pragma unroll
                for (int db = 0; db < 8; db++) {
                    int m4 = lane >> 3;
                    int j = ks*16 + (m4 & 1)*8 + (lane & 7);
                    int un = (db & 3)*2 + (m4 >> 1);
                    uint32_t off = (db >> 2)*8192 + j*128 + ((un ^ (j & 7))*16);
                    uint32_t Vh4[4];
                    ldsm4t(Vh4, vb + off);
                    mma_f16(yac[db*2],   pH[ks], Vh4);
                    mma_f16(yac[db*2+1], pH[ks], Vh4+2);
                }
            }
        }

        __syncthreads();   // stage (c%3) free for reuse at iteration c+3
    }

    // epilogue: normalize, write fp16 [B,T,C]
    const int b = bh >> 4, h = bh & 15;
    #pragma unroll
    for (int rh = 0; rh < 2; rh++) {
        float inv = 1.f / li[rh];
        int t = gq0 + (lane >> 2) + rh*8;
        size_t rowo = ((size_t)(b*TT + t))*CC + h*DD;
        #pragma unroll
        for (int nf = 0; nf < 16; nf++) {
            int col = nf*8 + 2*(lane & 3);
            __half2 hp;
            hp.x = __float2half(yac[nf][rh*2]*inv);
            hp.y = __float2half(yac[nf][rh*2+1]*inv);
            *(__half2*)(g_yh + rowo + col) = hp;
        }
    }
}

// ===========================================================================
extern "C" void kernel_launch(void* const* d_in, const int* in_sizes, int n_in,
                              void* d_out, int out_size)
{
    const float* x     = (const float*)d_in[0];
    const float* w_qkv = (const float*)d_in[1];
    const float* w_out = (const float*)d_in[2];
    float* out = (float*)d_out;

    __half *qkv16, *xh, *yh, *wqh, *woh;
    cudaGetSymbolAddress((void**)&qkv16, g_qkv16);
    cudaGetSymbolAddress((void**)&xh, g_xh);
    cudaGetSymbolAddress((void**)&yh, g_yh);
    cudaGetSymbolAddress((void**)&wqh, g_wqt_h);
    cudaGetSymbolAddress((void**)&woh, g_wot_h);

    static int attr_set = 0;
    if (!attr_set) {
        cudaFuncSetAttribute(gemm_hmma_kernel<float>,
                             cudaFuncAttributeMaxDynamicSharedMemorySize, GH_SMEM);
        cudaFuncSetAttribute(gemm_hmma_kernel<__half>,
                             cudaFuncAttributeMaxDynamicSharedMemorySize, GH_SMEM);
        cudaFuncSetAttribute(attn_hmma_kernel,
                             cudaFuncAttributeMaxDynamicSharedMemorySize, ATT_SMEM);
        attr_set = 1;
    }

    init_invfreq_kernel<<<1, 64>>>();

    convert_kernel<<<(MM*CC + 255)/256, 256>>>(x, xh, MM*CC);
    transpose_split_kernel<<<dim3(N_QKV/32, CC/32), 256>>>(w_qkv, wqh, CC, N_QKV);
    transpose_split_kernel<<<dim3(CC/32, CC/32), 256>>>(w_out, woh, CC, CC);

    // qkv = x @ w_qkv  (fp16 output)
    gemm_hmma_kernel<__half><<<dim3(N_QKV/128, MM/128), 256, GH_SMEM>>>(
        xh, wqh, qkv16, MM, N_QKV, CC);

    // RoPE pair-wise -> q/k/v fp16 [B,H,T,D]
    rope_kernel<<<(MM*512)/256, 256>>>();

    // fp16 flash attention -> yh [B,T,C]
    attn_hmma_kernel<<<dim3(TT/AQ, BB*HH), 256, ATT_SMEM>>>();

    // out = y @ w_out  (fp32 output)
    gemm_hmma_kernel<float><<<dim3(CC/128, MM/128), 256, GH_SMEM>>>(
        yh, woh, out, MM, CC, CC);
}

// round 14
// speedup vs baseline: 1.9425x; 1.0555x over previous
#include <cuda_runtime.h>
#include <cuda_fp16.h>
#include <cstdint>
#include <math.h>

// Problem constants
#define BB 2
#define TT 2048
#define CC 2048
#define HH 16
#define DD 128
#define MM (BB*TT)          // 4096
#define N_QKV (3*CC)        // 6144

// Scratch (static device globals; no runtime allocation allowed)
__device__ float g_invfreq[DD/2];

// fp16 operands
__device__ __half g_xh[(size_t)MM * CC];
__device__ __half g_yh[(size_t)MM * CC];         // attention out [B,T,C]
__device__ __half g_wqt_h[(size_t)N_QKV * CC];   // w_qkv^T [N,K]
__device__ __half g_wot_h[(size_t)CC * CC];      // w_out^T
__device__ __half g_qpre[(size_t)MM * CC];       // pre-rope q [B,H,T,D]
__device__ __half g_kpre[(size_t)MM * CC];       // pre-rope k [B,H,T,D]
__device__ __half g_qh[(size_t)MM * CC];         // roped q [B,H,T,D]
__device__ __half g_kh[(size_t)MM * CC];
__device__ __half g_vh[(size_t)MM * CC];         // v (written by GEMM1 epilogue)

// ===========================================================================
__device__ __forceinline__ uint32_t smem_u32(const void* p) {
    uint32_t a;
    asm("{ .reg .u64 t; cvta.to.shared.u64 t, %1; cvt.u32.u64 %0, t; }"
        : "=r"(a) : "l"(p));
    return a;
}
#define CP_ASYNC16(dst, src) \
    asm volatile("cp.async.cg.shared.global [%0], [%1], 16;" :: "r"(dst), "l"(src))
#define CP_COMMIT() asm volatile("cp.async.commit_group;" ::: "memory")
#define CP_WAIT(n)  asm volatile("cp.async.wait_group %0;" :: "n"(n) : "memory")

__device__ __forceinline__ void ldsm4(uint32_t* r, uint32_t addr) {
    asm volatile("ldmatrix.sync.aligned.m8n8.x4.shared.b16 {%0,%1,%2,%3}, [%4];"
        : "=r"(r[0]), "=r"(r[1]), "=r"(r[2]), "=r"(r[3]) : "r"(addr));
}
__device__ __forceinline__ void ldsm4t(uint32_t* r, uint32_t addr) {
    asm volatile("ldmatrix.sync.aligned.m8n8.x4.trans.shared.b16 {%0,%1,%2,%3}, [%4];"
        : "=r"(r[0]), "=r"(r[1]), "=r"(r[2]), "=r"(r[3]) : "r"(addr));
}
__device__ __forceinline__ void mma_f16(float* d, const uint32_t* a, const uint32_t* b) {
    asm volatile("mma.sync.aligned.m16n8k16.row.col.f32.f16.f16.f32 "
        "{%0,%1,%2,%3}, {%4,%5,%6,%7}, {%8,%9}, {%0,%1,%2,%3};"
        : "+f"(d[0]), "+f"(d[1]), "+f"(d[2]), "+f"(d[3])
        : "r"(a[0]), "r"(a[1]), "r"(a[2]), "r"(a[3]), "r"(b[0]), "r"(b[1]));
}

// ===========================================================================
__global__ void init_invfreq_kernel() {
    int i = threadIdx.x;
    if (i < DD/2) {
        double e = (double)(2*i) / (double)DD;
        g_invfreq[i] = (float)(1.0 / pow(10000.0, e));
    }
}

// ===========================================================================
// Merged preprocessing: x convert (vectorized) + both weight transposes
// (half2 write phase for full store rate). One launch.
// Block ranges: [0,8192) convert; [8192,20480) w_qkv^T; [20480,24576) w_out^T.
// ===========================================================================
__device__ __forceinline__ void transpose_tile32(
    const float* __restrict__ W, __half* __restrict__ Th,
    int K, int N, int bx, int by, float (*tile)[33])
{
    int tid = threadIdx.x;
    int n0 = bx*32, k0 = by*32;
    int tx = tid & 31, ty = tid >> 5;
    #pragma unroll
    for (int r = 0; r < 4; r++)
        tile[ty + r*8][tx] = W[(size_t)(k0 + ty + r*8)*N + n0 + tx];
    __syncthreads();
    int kx = (tid & 15)*2, ny = tid >> 4;
    #pragma unroll
    for (int r = 0; r < 2; r++) {
        int nn = ny + r*16;
        __half2 h = __floats2half2_rn(tile[kx][nn], tile[kx+1][nn]);
        *(__half2*)(Th + (size_t)(n0 + nn)*K + k0 + kx) = h;
    }
}

#define PREP_BLOCKS (8192 + 12288 + 4096)

__global__ __launch_bounds__(256)
void prep_kernel(const float* __restrict__ x,
                 const float* __restrict__ w_qkv,
                 const float* __restrict__ w_out)
{
    __shared__ float tile[32][33];
    int bid = blockIdx.x;
    if (bid < 8192) {
        int i = (bid*256 + threadIdx.x)*4;
        float4 v = *(const float4*)(x + i);
        *(__half2*)(g_xh + i)     = __floats2half2_rn(v.x, v.y);
        *(__half2*)(g_xh + i + 2) = __floats2half2_rn(v.z, v.w);
    } else if (bid < 8192 + 12288) {
        int lb = bid - 8192;               // nx = 6144/32 = 192
        transpose_tile32(w_qkv, g_wqt_h, CC, N_QKV, lb % 192, lb / 192, tile);
    } else {
        int lb = bid - 20480;              // nx = 2048/32 = 64
        transpose_tile32(w_out, g_wot_h, CC, CC, lb % 64, lb / 64, tile);
    }
}

// ===========================================================================
// HMMA fp16 GEMM, 3-stage cp.async pipeline.
// CTA tile 128x128, 256 threads (8 warps 2x4), warp tile 64x32, KC=64.
// PERM=1 (GEMM1): epilogue writes fp16 permuted to [B,H,T,D]:
//   N-tile = one (matrix, head); q->g_qpre, k->g_kpre, v->g_vh (final).
// PERM=0 (GEMM2): fp32 row-major to C.
// ===========================================================================
#define KC 64
#define GT_B 16384
#define STAGE_B (2*GT_B)      // 32768
#define GH_SMEM (3*STAGE_B)   // 98304

template<int PERM>
__global__ __launch_bounds__(256, 2)
void gemm_hmma_kernel(const __half* __restrict__ Ah,
                      const __half* __restrict__ Bh,
                      float* __restrict__ C, int M, int N, int K)
{
    extern __shared__ char sm[];
    const uint32_t sbase = smem_u32(sm);

    const int tid  = threadIdx.x;
    const int wid  = tid >> 5;
    const int lane = tid & 31;
    const int wm = wid >> 2;
    const int wn = wid & 3;
    const int bm = blockIdx.y * 128;
    const int bn = blockIdx.x * 128;

    const __half* srcs[2] = { Ah + (size_t)bm*K, Bh + (size_t)bn*K };

    const int aRowB = wm*64 + (lane & 7) + ((lane >> 3) & 1)*8;
    const int aCH   = lane >> 4;
    const int bRowB = wn*32 + ((lane >> 4) & 1)*8 + (lane & 7);
    const int bCH   = (lane >> 3) & 1;

    float acc[4][4][4];
    #pragma unroll
    for (int mt = 0; mt < 4; mt++)
        #pragma unroll
        for (int nt = 0; nt < 4; nt++)
            #pragma unroll
            for (int e = 0; e < 4; e++) acc[mt][nt][e] = 0.f;

    auto load_stage = [&](int buf, int kc) {
        uint32_t stg = sbase + buf*STAGE_B;
        #pragma unroll
        for (int t = 0; t < 2; t++) {
            const __half* sp = srcs[t] + kc*KC;
            uint32_t db = stg + t*GT_B;
            #pragma unroll
            for (int e = 0; e < 4; e++) {
                int idx = e*256 + tid;
                int row = idx >> 3, u = idx & 7;
                uint32_t d = db + row*128 + ((u ^ (row & 7))*16);
                CP_ASYNC16(d, sp + (size_t)row*K + u*8);
            }
        }
    };

    const int nch = K / KC;
    load_stage(0, 0);
    CP_COMMIT();
    load_stage(1, 1);
    CP_COMMIT();

    for (int c = 0; c < nch; c++) {
        if (c + 2 < nch) {
            load_stage((c+2) % 3, c+2);
            CP_COMMIT();
            CP_WAIT(2);
        } else if (c + 1 < nch) {
            CP_WAIT(1);
        } else {
            CP_WAIT(0);
        }
        __syncthreads();

        const uint32_t stg = sbase + (c % 3)*STAGE_B;

        #pragma unroll
        for (int ks = 0; ks < 4; ks++) {
            uint32_t ah[4][4], bh[2][4];
            #pragma unroll
            for (int mt = 0; mt < 4; mt++) {
                int r = aRowB + mt*16;
                uint32_t off = r*128 + (((ks*2 + aCH) ^ (r & 7))*16);
                ldsm4(ah[mt], stg + off);
            }
            #pragma unroll
            for (int nt2 = 0; nt2 < 2; nt2++) {
                int r = bRowB + nt2*16;
                uint32_t off = r*128 + (((ks*2 + bCH) ^ (r & 7))*16);
                ldsm4(bh[nt2], stg + GT_B + off);
            }
            #pragma unroll
            for (int mt = 0; mt < 4; mt++) {
                #pragma unroll
                for (int nt = 0; nt < 4; nt++) {
                    const uint32_t* bhp = &bh[nt >> 1][(nt & 1)*2];
                    mma_f16(acc[mt][nt], ah[mt], bhp);
                }
            }
        }
        __syncthreads();
    }

    if (PERM) {
        const int mat = bn >> 11;              // 0=q, 1=k, 2=v
        const int h   = (bn & 2047) >> 7;
        const int b   = bm >> 11;
        __half* dst = (mat == 0) ? g_qpre : (mat == 1) ? g_kpre : g_vh;
        #pragma unroll
        for (int mt = 0; mt < 4; mt++) {
            #pragma unroll
            for (int nt = 0; nt < 4; nt++) {
                int r0 = bm + wm*64 + mt*16 + (lane >> 2);
                int t  = r0 & (TT-1);
                int cl = wn*32 + nt*8 + (lane & 3)*2;
                size_t o = (((size_t)(b*HH + h))*TT + t)*DD + cl;
                *(__half2*)(dst + o) =
                    __floats2half2_rn(acc[mt][nt][0], acc[mt][nt][1]);
                *(__half2*)(dst + o + 8*DD) =
                    __floats2half2_rn(acc[mt][nt][2], acc[mt][nt][3]);
            }
        }
    } else {
        #pragma unroll
        for (int mt = 0; mt < 4; mt++) {
            #pragma unroll
            for (int nt = 0; nt < 4; nt++) {
                int r0 = bm + wm*64 + mt*16 + (lane >> 2);
                int c0 = bn + wn*32 + nt*8 + (lane & 3)*2;
                *(float2*)(C + (size_t)r0*N + c0) =
                    make_float2(acc[mt][nt][0], acc[mt][nt][1]);
                *(float2*)(C + (size_t)(r0+8)*N + c0) =
                    make_float2(acc[mt][nt][2], acc[mt][nt][3]);
            }
        }
    }
}

// ===========================================================================
// RoPE on q/k only, already in [B,H,T,D] fp16. One thread per d-pair,
// handles both q and k (shared sincos). v untouched (already final).
// Threads total: B*H*T*32 = 2,097,152.
// ===========================================================================
__global__ __launch_bounds__(256)
void rope_kernel()
{
    int idx = blockIdx.x*256 + threadIdx.x;
    int d2 = (idx & 31)*2;
    int t  = (idx >> 5) & (TT-1);
    int bh = idx >> 16;

    float sn0, cs0, sn1, cs1;
    sincosf((float)t * g_invfreq[d2],   &sn0, &cs0);
    sincosf((float)t * g_invfreq[d2+1], &sn1, &cs1);

    size_t o = ((size_t)bh*TT + t)*DD + d2;

    {
        float2 lo = __half22float2(*(const __half2*)(g_qpre + o));
        float2 up = __half22float2(*(const __half2*)(g_qpre + o + 64));
        *(__half2*)(g_qh + o)      = __floats2half2_rn(lo.x*cs0 - up.x*sn0,
                                                       lo.y*cs1 - up.y*sn1);
        *(__half2*)(g_qh + o + 64) = __floats2half2_rn(up.x*cs0 + lo.x*sn0,
                                                       up.y*cs1 + lo.y*sn1);
    }
    {
        float2 lo = __half22float2(*(const __half2*)(g_kpre + o));
        float2 up = __half22float2(*(const __half2*)(g_kpre + o + 64));
        *(__half2*)(g_kh + o)      = __floats2half2_rn(lo.x*cs0 - up.x*sn0,
                                                       lo.y*cs1 - up.y*sn1);
        *(__half2*)(g_kh + o + 64) = __floats2half2_rn(up.x*cs0 + lo.x*sn0,
                                                       up.y*cs1 + lo.y*sn1);
    }
}

// ===========================================================================
// HMMA fp16 flash attention (unchanged from R13).
// ===========================================================================
#define AQ 128
#define AK 64
#define SM_Q 32768
#define STG_SZ 32768
#define ATT_SMEM (SM_Q + 3*STG_SZ)   // 131072

__global__ __launch_bounds__(256, 1)
void attn_hmma_kernel()
{
    extern __shared__ char sm[];
    const uint32_t sb = smem_u32(sm);
    const int tid = threadIdx.x, wid = tid >> 5, lane = tid & 31;

    const int qt  = (TT/AQ - 1) - blockIdx.x;
    const int bh  = blockIdx.y;
    const int qt0 = qt * AQ;
    const size_t base = (size_t)bh * TT * DD;
    const __half *qhp = g_qh + base;
    const __half *khp = g_kh + base;
    const __half *vhp = g_vh + base;

    #pragma unroll
    for (int e = 0; e < 8; e++) {
        int idx = e*256 + tid;
        int r   = (idx >> 4) & 127;
        int ug  = idx & 15;
        int h2 = ug >> 3, u = ug & 7;
        uint32_t dst = sb + h2*16384 + r*128 + ((u ^ (r & 7))*16);
        CP_ASYNC16(dst, qhp + (size_t)(qt0 + r)*DD + ug*8);
    }

    const int nch = 2*qt + 2;

    auto load_stage = [&](int buf, int j0) {
        uint32_t stg = sb + SM_Q + buf*STG_SZ;
        #pragma unroll
        for (int e = 0; e < 4; e++) {
            int idx = e*256 + tid;
            int r   = (idx >> 4) & 63;
            int ug  = idx & 15;
            int h2 = ug >> 3, u = ug & 7;
            uint32_t dst = stg + h2*8192 + r*128 + ((u ^ (r & 7))*16);
            CP_ASYNC16(dst, khp + (size_t)(j0 + r)*DD + ug*8);
        }
        #pragma unroll
        for (int e = 0; e < 4; e++) {
            int idx = e*256 + tid;
            int r   = (idx >> 4) & 63;
            int ug  = idx & 15;
            int h2 = ug >> 3, u = ug & 7;
            uint32_t dst = stg + 16384 + h2*8192 + r*128 + ((u ^ (r & 7))*16);
            CP_ASYNC16(dst, vhp + (size_t)(j0 + r)*DD + ug*8);
        }
    };

    load_stage(0, 0);
    CP_COMMIT();
    if (nch > 1) { load_stage(1, AK); CP_COMMIT(); }

    const int rowblk = (wid < 4) ? wid : (11 - wid);
    const int wrow0 = rowblk * 16;
    const int gq0 = qt0 + wrow0;

    float yac[16][4];
    #pragma unroll
    for (int nf = 0; nf < 16; nf++)
        #pragma unroll
        for (int e = 0; e < 4; e++) yac[nf][e] = 0.f;
    float mi[2] = {-1e30f, -1e30f}, li[2] = {0.f, 0.f};

    uint32_t Qfrag[2][4][4];

    const float scale = 0.08838834764831845f;

    for (int c = 0; c < nch; c++) {
        const int j0 = c * AK;

        if (c + 2 < nch) {
            load_stage((c+2) % 3, (c+2)*AK);
            CP_COMMIT();
            CP_WAIT(2);
        } else if (c + 1 < nch) {
            CP_WAIT(1);
        } else {
            CP_WAIT(0);
        }
        __syncthreads();

        if (c == 0) {
            #pragma unroll
            for (int kh2 = 0; kh2 < 2; kh2++) {
                uint32_t qb = sb + kh2*16384;
                #pragma unroll
                for (int ks = 0; ks < 4; ks++) {
                    int ar = wrow0 + (lane & 7) + ((lane >> 3) & 1)*8;
                    int au = ks*2 + (lane >> 4);
                    uint32_t aoff = ar*128 + ((au ^ (ar & 7))*16);
                    ldsm4(Qfrag[kh2][ks], qb + aoff);
                }
            }
        }

        const uint32_t stg = sb + SM_Q + (c % 3)*STG_SZ;

        if (j0 < gq0 + 16) {
            float sa[8][4];
            #pragma unroll
            for (int nf = 0; nf < 8; nf++)
                #pragma unroll
                for (int e = 0; e < 4; e++) sa[nf][e] = 0.f;

            #pragma unroll
            for (int kh2 = 0; kh2 < 2; kh2++) {
                uint32_t kb = stg + kh2*8192;
                #pragma unroll
                for (int ks = 0; ks < 4; ks++) {
                    int br_ = ((lane >> 4) & 1)*8 + (lane & 7);
                    int bu  = ks*2 + ((lane >> 3) & 1);
                    #pragma unroll
                    for (int nb = 0; nb < 4; nb++) {
                        int r = br_ + nb*16;
                        uint32_t boff = r*128 + ((bu ^ (r & 7))*16);
                        uint32_t Kh4[4];
                        ldsm4(Kh4, kb + boff);
                        mma_f16(sa[2*nb],   Qfrag[kh2][ks], Kh4);
                        mma_f16(sa[2*nb+1], Qfrag[kh2][ks], Kh4+2);
                    }
                }
            }

            #pragma unroll
            for (int nf = 0; nf < 8; nf++)
                #pragma unroll
                for (int e = 0; e < 4; e++) sa[nf][e] *= scale;
            if (j0 + 63 > gq0) {
                #pragma unroll
                for (int nf = 0; nf < 8; nf++)
                    #pragma unroll
                    for (int e = 0; e < 4; e++) {
                        int row = gq0 + (lane >> 2) + (e >> 1)*8;
                        int col = j0 + nf*8 + 2*(lane & 3) + (e & 1);
                        if (col > row) sa[nf][e] = -1e30f;
                    }
            }

            #pragma unroll
            for (int rh = 0; rh < 2; rh++) {
                float m = -1e30f;
                #pragma unroll
                for (int nf = 0; nf < 8; nf++)
                    m = fmaxf(m, fmaxf(sa[nf][rh*2], sa[nf][rh*2+1]));
                m = fmaxf(m, __shfl_xor_sync(0xffffffffu, m, 1));
                m = fmaxf(m, __shfl_xor_sync(0xffffffffu, m, 2));
                float mnew = fmaxf(mi[rh], m);
                float corr = __expf(mi[rh] - mnew);
                float rs = 0.f;
                #pragma unroll
                for (int nf = 0; nf < 8; nf++) {
                    float p0 = __expf(sa[nf][rh*2]   - mnew);
                    float p1 = __expf(sa[nf][rh*2+1] - mnew);
                    sa[nf][rh*2] = p0; sa[nf][rh*2+1] = p1;
                    rs += p0 + p1;
                }
                rs += __shfl_xor_sync(0xffffffffu, rs, 1);
                rs += __shfl_xor_sync(0xffffffffu, rs, 2);
                li[rh] = li[rh]*corr + rs;
                mi[rh] = mnew;
                #pragma unroll
                for (int nf = 0; nf < 16; nf++) {
                    yac[nf][rh*2]   *= corr;
                    yac[nf][rh*2+1] *= corr;
                }
            }

            uint32_t pH[4][4];
            #pragma unroll
            for (int j = 0; j < 4; j++) {
                #pragma unroll
                for (int q = 0; q < 4; q++) {
                    int f = 2*j + (q >> 1);
                    int o = (q & 1)*2;
                    __half2 hp;
                    hp.x = __float2half(sa[f][o]);
                    hp.y = __float2half(sa[f][o+1]);
                    pH[j][q] = *(uint32_t*)&hp;
                }
            }

            const uint32_t vb = stg + 16384;
            #pragma unroll
            for (int ks = 0; ks < 4; ks++) {
                #pragma unroll
                for (int db = 0; db < 8; db++) {
                    int m4 = lane >> 3;
                    int j = ks*16 + (m4 & 1)*8 + (lane & 7);
                    int un = (db & 3)*2 + (m4 >> 1);
                    uint32_t off = (db >> 2)*8192 + j*128 + ((un ^ (j & 7))*16);
                    uint32_t Vh4[4];
                    ldsm4t(Vh4, vb + off);
                    mma_f16(yac[db*2],   pH[ks], Vh4);
                    mma_f16(yac[db*2+1], pH[ks], Vh4+2);
                }
            }
        }

        __syncthreads();
    }

    const int b = bh >> 4, h = bh & 15;
    #pragma unroll
    for (int rh = 0; rh < 2; rh++) {
        float inv = 1.f / li[rh];
        int t = gq0 + (lane >> 2) + rh*8;
        size_t rowo = ((size_t)(b*TT + t))*CC + h*DD;
        #pragma unroll
        for (int nf = 0; nf < 16; nf++) {
            int col = nf*8 + 2*(lane & 3);
            __half2 hp;
            hp.x = __float2half(yac[nf][rh*2]*inv);
            hp.y = __float2half(yac[nf][rh*2+1]*inv);
            *(__half2*)(g_yh + rowo + col) = hp;
        }
    }
}

// ===========================================================================
extern "C" void kernel_launch(void* const* d_in, const int* in_sizes, int n_in,
                              void* d_out, int out_size)
{
    const float* x     = (const float*)d_in[0];
    const float* w_qkv = (const float*)d_in[1];
    const float* w_out = (const float*)d_in[2];
    float* out = (float*)d_out;

    __half *xh, *yh, *wqh, *woh;
    cudaGetSymbolAddress((void**)&xh, g_xh);
    cudaGetSymbolAddress((void**)&yh, g_yh);
    cudaGetSymbolAddress((void**)&wqh, g_wqt_h);
    cudaGetSymbolAddress((void**)&woh, g_wot_h);

    static int attr_set = 0;
    if (!attr_set) {
        cudaFuncSetAttribute(gemm_hmma_kernel<0>,
                             cudaFuncAttributeMaxDynamicSharedMemorySize, GH_SMEM);
        cudaFuncSetAttribute(gemm_hmma_kernel<1>,
                             cudaFuncAttributeMaxDynamicSharedMemorySize, GH_SMEM);
        cudaFuncSetAttribute(attn_hmma_kernel,
                             cudaFuncAttributeMaxDynamicSharedMemorySize, ATT_SMEM);
        attr_set = 1;
    }

    init_invfreq_kernel<<<1, 64>>>();

    // merged preprocessing: convert x + transpose both weights
    prep_kernel<<<PREP_BLOCKS, 256>>>(x, w_qkv, w_out);

    // qkv = x @ w_qkv, epilogue writes permuted q/k (pre-rope) and final v
    gemm_hmma_kernel<1><<<dim3(N_QKV/128, MM/128), 256, GH_SMEM>>>(
        xh, wqh, nullptr, MM, N_QKV, CC);

    // RoPE on q/k only
    rope_kernel<<<(BB*HH*TT*32)/256, 256>>>();

    // fp16 flash attention -> yh [B,T,C]
    attn_hmma_kernel<<<dim3(TT/AQ, BB*HH), 256, ATT_SMEM>>>();

    // out = y @ w_out  (fp32 output)
    gemm_hmma_kernel<0><<<dim3(CC/128, MM/128), 256, GH_SMEM>>>(
        yh, woh, out, MM, CC, CC);
}